// round 11
// baseline (speedup 1.0000x reference)
#include <cuda_runtime.h>
#include <math.h>

#define BB    4
#define S     1024
#define D     1024
#define H     16
#define HD    64
#define M_TOT (BB * S)          /* 4096 */
#define SCALE 0.125f            /* 1/sqrt(64) */

/* ---------------- scratch (device globals; no allocation) ---------------- */
__device__ __align__(128) float g_q[M_TOT * D];                 /* 16 MB */
__device__ __align__(128) float g_k[M_TOT * D];                 /* 16 MB */
__device__ __align__(128) float g_v[M_TOT * D];                 /* 16 MB */
__device__ __align__(128) float g_att[M_TOT * D];               /* 16 MB */
__device__ __align__(128) float g_sc[(size_t)BB * H * S * S];   /* 256 MB */

/* ---------------- generic SGEMM + bias: C[M,N] = A[M,K] @ W[K,N] + b -----
   BM=BN=128, BK=16, 256 threads, 8x8 register microtile. ------------------ */
__global__ __launch_bounds__(256) void sgemm_bias(
    const float* __restrict__ A, const float* __restrict__ W,
    const float* __restrict__ bias, float* __restrict__ C,
    int K, int N)
{
    __shared__ float As[16][128];
    __shared__ float Bs[16][128];
    const int tid = threadIdx.x;
    const int m0 = blockIdx.y * 128;
    const int n0 = blockIdx.x * 128;

    const int a_row = tid >> 2;           /* 0..63  */
    const int a_k   = (tid & 3) << 2;     /* 0,4,8,12 */
    const int b_k   = tid >> 5;           /* 0..7   */
    const int b_col = (tid & 31) << 2;    /* 0..124 */
    const int tm    = (tid >> 4) << 3;
    const int tn    = (tid & 15) << 3;

    float acc[8][8];
#pragma unroll
    for (int i = 0; i < 8; i++)
#pragma unroll
        for (int j = 0; j < 8; j++) acc[i][j] = 0.f;

    for (int k0 = 0; k0 < K; k0 += 16) {
#pragma unroll
        for (int rr = 0; rr < 2; rr++) {
            int row = a_row + rr * 64;
            float4 av = *(const float4*)(A + (size_t)(m0 + row) * K + k0 + a_k);
            As[a_k + 0][row] = av.x; As[a_k + 1][row] = av.y;
            As[a_k + 2][row] = av.z; As[a_k + 3][row] = av.w;
        }
#pragma unroll
        for (int rr = 0; rr < 2; rr++) {
            int kk = b_k + rr * 8;
            *(float4*)(&Bs[kk][b_col]) =
                *(const float4*)(W + (size_t)(k0 + kk) * N + n0 + b_col);
        }
        __syncthreads();
#pragma unroll
        for (int kk = 0; kk < 16; kk++) {
            float a[8], b[8];
            *(float4*)(a)     = *(const float4*)&As[kk][tm];
            *(float4*)(a + 4) = *(const float4*)&As[kk][tm + 4];
            *(float4*)(b)     = *(const float4*)&Bs[kk][tn];
            *(float4*)(b + 4) = *(const float4*)&Bs[kk][tn + 4];
#pragma unroll
            for (int i = 0; i < 8; i++)
#pragma unroll
                for (int j = 0; j < 8; j++)
                    acc[i][j] = fmaf(a[i], b[j], acc[i][j]);
        }
        __syncthreads();
    }

#pragma unroll
    for (int i = 0; i < 8; i++) {
#pragma unroll
        for (int j = 0; j < 8; j += 4) {
            float4 o;
            o.x = acc[i][j + 0] + bias[n0 + tn + j + 0];
            o.y = acc[i][j + 1] + bias[n0 + tn + j + 1];
            o.z = acc[i][j + 2] + bias[n0 + tn + j + 2];
            o.w = acc[i][j + 3] + bias[n0 + tn + j + 3];
            *(float4*)(C + (size_t)(m0 + tm + i) * N + n0 + tn + j) = o;
        }
    }
}

/* ---------------- scores: content + skewed relative position -------------
   Lower-triangular 64x64 tiles only. For j<=i:
     score[i,j] = scale * sum_d q[i,d] * (k[j,d] + rel[S-1-(i-j), d])
   Masked entries of diagonal tiles are written as 0.
   Shared layouts are d-major so the inner-d loop reads are conflict-free. */
__global__ __launch_bounds__(256) void scores_kernel(const float* __restrict__ rel_tab)
{
    __shared__ float qs[16][64];
    __shared__ float ks[16][64];
    __shared__ float rs[16][128];

    const int bh = blockIdx.y;
    const int b = bh / H, h = bh % H;

    /* decode lower-triangular tile index */
    int t = blockIdx.x, ti = 0;
    while (t >= ti + 1) { t -= ti + 1; ti++; }
    const int tj = t;
    const int i0 = ti * 64, j0 = tj * 64;
    const int lo = S - 64 - i0 + j0;   /* rel index of local r-row 0; >= 0 */

    const int tid = threadIdx.x;
    const int tx = tid & 15, ty = tid >> 4;
    const int q_li = tid >> 2,  q_dd = (tid & 3) << 2;
    const int r_li = tid >> 1,  r_dd = (tid & 1) << 3;
    const int base = 60 - 4 * ty + 4 * tx;   /* local r row base, 0..120, %4==0 */

    const float* qb = g_q + (size_t)(b * S + i0) * D + h * HD;
    const float* kb = g_k + (size_t)(b * S + j0) * D + h * HD;
    const float* rb = rel_tab + h * HD;

    float acc[4][4];
#pragma unroll
    for (int a = 0; a < 4; a++)
#pragma unroll
        for (int c = 0; c < 4; c++) acc[a][c] = 0.f;

    for (int d0 = 0; d0 < HD; d0 += 16) {
        {
            float4 qv = *(const float4*)(qb + (size_t)q_li * D + d0 + q_dd);
            qs[q_dd + 0][q_li] = qv.x; qs[q_dd + 1][q_li] = qv.y;
            qs[q_dd + 2][q_li] = qv.z; qs[q_dd + 3][q_li] = qv.w;
            float4 kv = *(const float4*)(kb + (size_t)q_li * D + d0 + q_dd);
            ks[q_dd + 0][q_li] = kv.x; ks[q_dd + 1][q_li] = kv.y;
            ks[q_dd + 2][q_li] = kv.z; ks[q_dd + 3][q_li] = kv.w;
            int rrow = lo + r_li; if (rrow > S - 1) rrow = S - 1; /* clamp: masked region only */
            const float* rp = rb + (size_t)rrow * D + d0 + r_dd;
            float4 r0v = *(const float4*)(rp);
            float4 r1v = *(const float4*)(rp + 4);
            rs[r_dd + 0][r_li] = r0v.x; rs[r_dd + 1][r_li] = r0v.y;
            rs[r_dd + 2][r_li] = r0v.z; rs[r_dd + 3][r_li] = r0v.w;
            rs[r_dd + 4][r_li] = r1v.x; rs[r_dd + 5][r_li] = r1v.y;
            rs[r_dd + 6][r_li] = r1v.z; rs[r_dd + 7][r_li] = r1v.w;
        }
        __syncthreads();
#pragma unroll
        for (int dd = 0; dd < 16; dd++) {
            float q4[4], k4[4], r8[8];
            *(float4*)(q4)     = *(const float4*)&qs[dd][4 * ty];
            *(float4*)(k4)     = *(const float4*)&ks[dd][4 * tx];
            *(float4*)(r8)     = *(const float4*)&rs[dd][base];
            *(float4*)(r8 + 4) = *(const float4*)&rs[dd][base + 4];
#pragma unroll
            for (int a = 0; a < 4; a++)
#pragma unroll
                for (int c = 0; c < 4; c++)
                    acc[a][c] = fmaf(q4[a], k4[c] + r8[3 - a + c], acc[a][c]);
        }
        __syncthreads();
    }

    float* outp = g_sc + (size_t)bh * S * S;
#pragma unroll
    for (int a = 0; a < 4; a++) {
        const int gi = i0 + 4 * ty + a;
        const int gj0 = j0 + 4 * tx;
        float4 o;
        o.x = (gj0 + 0 <= gi) ? acc[a][0] * SCALE : 0.f;
        o.y = (gj0 + 1 <= gi) ? acc[a][1] * SCALE : 0.f;
        o.z = (gj0 + 2 <= gi) ? acc[a][2] * SCALE : 0.f;
        o.w = (gj0 + 3 <= gi) ? acc[a][3] * SCALE : 0.f;
        *(float4*)(outp + (size_t)gi * S + gj0) = o;
    }
}

/* ---------------- causal row softmax (in place) --------------------------- */
__global__ __launch_bounds__(256) void softmax_kernel()
{
    const int row = blockIdx.x;         /* bh*S + i */
    const int i = row & (S - 1);
    float* base = g_sc + (size_t)row * S;
    const int tid = threadIdx.x;

    __shared__ float red[8];
    float v[4];
    float mx = -1e30f;
#pragma unroll
    for (int u = 0; u < 4; u++) {
        int j = tid + (u << 8);
        v[u] = (j <= i) ? base[j] : -1e30f;
        mx = fmaxf(mx, v[u]);
    }
#pragma unroll
    for (int o = 16; o > 0; o >>= 1)
        mx = fmaxf(mx, __shfl_xor_sync(0xffffffffu, mx, o));
    if ((tid & 31) == 0) red[tid >> 5] = mx;
    __syncthreads();
    float bm = red[0];
#pragma unroll
    for (int w = 1; w < 8; w++) bm = fmaxf(bm, red[w]);

    float sum = 0.f;
#pragma unroll
    for (int u = 0; u < 4; u++) {
        int j = tid + (u << 8);
        float e = (j <= i) ? __expf(v[u] - bm) : 0.f;
        v[u] = e;
        sum += e;
    }
#pragma unroll
    for (int o = 16; o > 0; o >>= 1)
        sum += __shfl_xor_sync(0xffffffffu, sum, o);
    __syncthreads();                     /* red reuse */
    if ((tid & 31) == 0) red[tid >> 5] = sum;
    __syncthreads();
    float tot = 0.f;
#pragma unroll
    for (int w = 0; w < 8; w++) tot += red[w];
    const float inv = 1.f / tot;

#pragma unroll
    for (int u = 0; u < 4; u++) {
        int j = tid + (u << 8);
        if (j <= i) base[j] = v[u] * inv;
    }
}

/* ---------------- AV: out[b,i,h*64+d] = sum_{j<=i} w[i,j] * v[b,j,h*64+d] -
   Causal: only key tiles jt <= ti (diagonal tile upper part is 0-filled). -- */
__global__ __launch_bounds__(256) void av_kernel()
{
    __shared__ float ws[64][68];
    __shared__ float vs[64][68];

    const int bh = blockIdx.y;
    const int b = bh / H, h = bh % H;
    const int ti = blockIdx.x;
    const int i0 = ti * 64;
    const int tid = threadIdx.x;
    const int tx = tid & 15, ty = tid >> 4;
    const int lrow = tid >> 2, lc4 = (tid & 3) << 2;

    const float* wbase = g_sc + (size_t)bh * S * S;
    const float* vbase = g_v + (size_t)(b * S) * D + h * HD;

    float acc[4][4];
#pragma unroll
    for (int a = 0; a < 4; a++)
#pragma unroll
        for (int c = 0; c < 4; c++) acc[a][c] = 0.f;

    for (int jt = 0; jt <= ti; jt++) {
        const int j0 = jt * 64;
#pragma unroll
        for (int u = 0; u < 4; u++) {
            *(float4*)&ws[lrow][lc4 + 16 * u] =
                *(const float4*)(wbase + (size_t)(i0 + lrow) * S + j0 + lc4 + 16 * u);
            *(float4*)&vs[lrow][lc4 + 16 * u] =
                *(const float4*)(vbase + (size_t)(j0 + lrow) * D + lc4 + 16 * u);
        }
        __syncthreads();
#pragma unroll
        for (int lj = 0; lj < 64; lj++) {
            float wv[4];
#pragma unroll
            for (int a = 0; a < 4; a++) wv[a] = ws[4 * ty + a][lj];
            float4 v4 = *(const float4*)&vs[lj][4 * tx];
            const float vv[4] = { v4.x, v4.y, v4.z, v4.w };
#pragma unroll
            for (int a = 0; a < 4; a++)
#pragma unroll
                for (int c = 0; c < 4; c++)
                    acc[a][c] = fmaf(wv[a], vv[c], acc[a][c]);
        }
        __syncthreads();
    }

    float* outb = g_att + (size_t)(b * S + i0) * D + h * HD;
#pragma unroll
    for (int a = 0; a < 4; a++) {
        float4 o;
        o.x = acc[a][0]; o.y = acc[a][1]; o.z = acc[a][2]; o.w = acc[a][3];
        *(float4*)(outb + (size_t)(4 * ty + a) * D + 4 * tx) = o;
    }
}

/* ---------------- launcher ------------------------------------------------ */
extern "C" void kernel_launch(void* const* d_in, const int* in_sizes, int n_in,
                              void* d_out, int out_size)
{
    (void)in_sizes; (void)n_in; (void)out_size;
    const float* query = (const float*)d_in[0];
    const float* key   = (const float*)d_in[1];
    const float* value = (const float*)d_in[2];
    /* d_in[3] = attention_mask (known causal triu; unused) */
    const float* Wq = (const float*)d_in[4];
    const float* bq = (const float*)d_in[5];
    const float* Wk = (const float*)d_in[6];
    const float* bk = (const float*)d_in[7];
    const float* Wv = (const float*)d_in[8];
    const float* bv = (const float*)d_in[9];
    const float* rel = (const float*)d_in[10];
    const float* Wo = (const float*)d_in[11];
    const float* bo = (const float*)d_in[12];

    float *qp, *kp, *vp, *ap;
    cudaGetSymbolAddress((void**)&qp, g_q);
    cudaGetSymbolAddress((void**)&kp, g_k);
    cudaGetSymbolAddress((void**)&vp, g_v);
    cudaGetSymbolAddress((void**)&ap, g_att);

    dim3 gproj(D / 128, M_TOT / 128);
    sgemm_bias<<<gproj, 256>>>(query, Wq, bq, qp, D, D);
    sgemm_bias<<<gproj, 256>>>(key,   Wk, bk, kp, D, D);
    sgemm_bias<<<gproj, 256>>>(value, Wv, bv, vp, D, D);

    scores_kernel<<<dim3(136, BB * H), 256>>>(rel);
    softmax_kernel<<<BB * H * S, 256>>>();
    av_kernel<<<dim3(S / 64, BB * H), 256>>>();

    sgemm_bias<<<gproj, 256>>>(ap, Wo, bo, (float*)d_out, D, D);
}

// round 13
// speedup vs baseline: 1.2577x; 1.2577x over previous
#include <cuda_runtime.h>
#include <cuda_bf16.h>
#include <math.h>
#include <stdint.h>

#define BB    4
#define S     1024
#define D     1024
#define H     16
#define HD    64
#define M_TOT (BB * S)          /* 4096 */
#define SCALE 0.125f            /* 1/sqrt(64) */

/* ---------------- scratch (device globals; no allocation) ---------------- */
__device__ __align__(128) float g_q[M_TOT * D];                 /* 16 MB */
__device__ __align__(128) float g_k[M_TOT * D];                 /* 16 MB */
__device__ __align__(128) float g_v[M_TOT * D];                 /* 16 MB */
__device__ __align__(128) float g_att[M_TOT * D];               /* 16 MB */
__device__ __align__(128) float g_sc[(size_t)BB * H * S * S];   /* 256 MB */

/* bf16 split staging for the tensor-core GEMMs (reused across all 4 GEMMs) */
__device__ __align__(128) __nv_bfloat16 s_ahi[(size_t)M_TOT * D];  /* 8 MB */
__device__ __align__(128) __nv_bfloat16 s_alo[(size_t)M_TOT * D];  /* 8 MB */
__device__ __align__(128) __nv_bfloat16 s_whi[(size_t)D * D];      /* 2 MB (W^T) */
__device__ __align__(128) __nv_bfloat16 s_wlo[(size_t)D * D];      /* 2 MB (W^T) */

/* ============ mma.sync bf16 GEMM: C[M,1024] = A @ W + bias ================
   A as bf16 hi/lo [M,1024] row-major; W as W^T hi/lo [1024 n][1024 k].
   K_ext = 3072 via segments: (Ah,Wh), (Al,Wh), (Ah,Wl).
   CTA 128x128, 4 warps (warp tile 64x64), BK=32, cp.async double buffer. */

__device__ __forceinline__ uint32_t smem_u32(const void* p) {
    uint32_t a;
    asm("{ .reg .u64 t; cvta.to.shared.u64 t, %1; cvt.u32.u64 %0, t; }"
        : "=r"(a) : "l"(p));
    return a;
}
__device__ __forceinline__ void cp16(uint32_t dst, const void* src) {
    asm volatile("cp.async.cg.shared.global [%0], [%1], 16;"
                 :: "r"(dst), "l"(src) : "memory");
}
__device__ __forceinline__ void mma16816(float* d, uint32_t a0, uint32_t a1,
                                         uint32_t a2, uint32_t a3,
                                         uint32_t b0, uint32_t b1) {
    asm volatile(
        "mma.sync.aligned.m16n8k16.row.col.f32.bf16.bf16.f32 "
        "{%0,%1,%2,%3}, {%4,%5,%6,%7}, {%8,%9}, {%0,%1,%2,%3};"
        : "+f"(d[0]), "+f"(d[1]), "+f"(d[2]), "+f"(d[3])
        : "r"(a0), "r"(a1), "r"(a2), "r"(a3), "r"(b0), "r"(b1));
}

__global__ __launch_bounds__(128) void gemm_mma(
    const __nv_bfloat16* __restrict__ ahi, const __nv_bfloat16* __restrict__ alo,
    const __nv_bfloat16* __restrict__ whi, const __nv_bfloat16* __restrict__ wlo,
    const float* __restrict__ bias, float* __restrict__ C)
{
    __shared__ __align__(16) __nv_bfloat16 As[2][128][40];
    __shared__ __align__(16) __nv_bfloat16 Ws[2][128][40];

    const int tid = threadIdx.x;
    const int wid = tid >> 5, l = tid & 31;
    const int m0 = blockIdx.y * 128, n0 = blockIdx.x * 128;
    const int m0w = (wid >> 1) * 64, n0w = (wid & 1) * 64;
    const int r = l >> 2, kk = (l & 3) * 2;

    const __nv_bfloat16* const segA[3] = { ahi, alo, ahi };
    const __nv_bfloat16* const segW[3] = { whi, whi, wlo };

    float acc[4][8][4];
#pragma unroll
    for (int mt = 0; mt < 4; mt++)
#pragma unroll
        for (int nt = 0; nt < 8; nt++)
#pragma unroll
            for (int e = 0; e < 4; e++) acc[mt][nt][e] = 0.f;

    /* each thread owns one row of each tile (tid = 0..127), 4x16B per row */
    auto load_stage = [&](int c, int st) {
        const int seg = c >> 5;
        const int kc = (c & 31) << 5;
        const __nv_bfloat16* Ap = segA[seg] + (size_t)(m0 + tid) * 1024 + kc;
        const __nv_bfloat16* Wp = segW[seg] + (size_t)(n0 + tid) * 1024 + kc;
        const uint32_t da = smem_u32(&As[st][tid][0]);
        const uint32_t dw = smem_u32(&Ws[st][tid][0]);
#pragma unroll
        for (int q = 0; q < 4; ++q) {
            cp16(da + q * 16, Ap + q * 8);
            cp16(dw + q * 16, Wp + q * 8);
        }
    };

    load_stage(0, 0);
    asm volatile("cp.async.commit_group;" ::: "memory");

    for (int c = 0; c < 96; ++c) {
        const int st = c & 1;
        if (c + 1 < 96) {
            load_stage(c + 1, st ^ 1);
            asm volatile("cp.async.commit_group;" ::: "memory");
            asm volatile("cp.async.wait_group 1;" ::: "memory");
        } else {
            asm volatile("cp.async.wait_group 0;" ::: "memory");
        }
        __syncthreads();

#pragma unroll
        for (int ko = 0; ko < 32; ko += 16) {
            uint32_t b[8][2];
#pragma unroll
            for (int nt = 0; nt < 8; ++nt) {
                b[nt][0] = *(const uint32_t*)&Ws[st][n0w + nt * 8 + r][kk + ko];
                b[nt][1] = *(const uint32_t*)&Ws[st][n0w + nt * 8 + r][kk + ko + 8];
            }
#pragma unroll
            for (int mt = 0; mt < 4; ++mt) {
                const int row = m0w + mt * 16 + r;
                /* a0=(r,k) a1=(r+8,k) a2=(r,k+8) a3=(r+8,k+8) */
                uint32_t a0 = *(const uint32_t*)&As[st][row][kk + ko];
                uint32_t a1 = *(const uint32_t*)&As[st][row + 8][kk + ko];
                uint32_t a2 = *(const uint32_t*)&As[st][row][kk + ko + 8];
                uint32_t a3 = *(const uint32_t*)&As[st][row + 8][kk + ko + 8];
#pragma unroll
                for (int nt = 0; nt < 8; ++nt)
                    mma16816(acc[mt][nt], a0, a1, a2, a3, b[nt][0], b[nt][1]);
            }
        }
        __syncthreads();
    }

    /* epilogue: c0,c1 -> (row, col..col+1); c2,c3 -> (row+8, ..) */
#pragma unroll
    for (int mt = 0; mt < 4; ++mt) {
        const int gm = m0 + m0w + mt * 16 + r;
#pragma unroll
        for (int nt = 0; nt < 8; ++nt) {
            const int gn = n0 + n0w + nt * 8 + kk;
            const float bx = bias[gn], by = bias[gn + 1];
            float2 o0 = { acc[mt][nt][0] + bx, acc[mt][nt][1] + by };
            float2 o1 = { acc[mt][nt][2] + bx, acc[mt][nt][3] + by };
            *(float2*)(C + (size_t)gm * 1024 + gn) = o0;
            *(float2*)(C + (size_t)(gm + 8) * 1024 + gn) = o1;
        }
    }
}

/* ------------- fp32 -> bf16 hi/lo split (A-side, elementwise) ------------- */
__global__ __launch_bounds__(256) void split_kernel(
    const float* __restrict__ src, __nv_bfloat16* __restrict__ hi,
    __nv_bfloat16* __restrict__ lo)
{
    const size_t i = (size_t)blockIdx.x * 256 + threadIdx.x; /* float4 index */
    float4 v = ((const float4*)src)[i];
    float f[4] = { v.x, v.y, v.z, v.w };
    uint32_t hw[2], lw[2];
#pragma unroll
    for (int p = 0; p < 2; ++p) {
        uint32_t h0 = 0, h1 = 0, l0 = 0, l1 = 0;
#pragma unroll
        for (int q = 0; q < 2; ++q) {
            float x = f[2 * p + q];
            __nv_bfloat16 hb = __float2bfloat16_rn(x);
            __nv_bfloat16 lb = __float2bfloat16_rn(x - __bfloat162float(hb));
            uint32_t hu = (uint32_t)__bfloat16_as_ushort(hb);
            uint32_t lu = (uint32_t)__bfloat16_as_ushort(lb);
            if (q == 0) { h0 = hu; l0 = lu; } else { h1 = hu; l1 = lu; }
        }
        hw[p] = h0 | (h1 << 16);
        lw[p] = l0 | (l1 << 16);
    }
    ((uint2*)hi)[i] = make_uint2(hw[0], hw[1]);
    ((uint2*)lo)[i] = make_uint2(lw[0], lw[1]);
}

/* ------------- W [K,N] -> W^T hi/lo bf16 [N,K] (transpose + split) -------- */
__global__ void wsplitT_kernel(const float* __restrict__ W,
                               __nv_bfloat16* __restrict__ hi,
                               __nv_bfloat16* __restrict__ lo)
{
    __shared__ float t[32][33];
    const int k0 = blockIdx.y * 32, n0 = blockIdx.x * 32;
    const int x = threadIdx.x, y = threadIdx.y;       /* 32 x 8 */
#pragma unroll
    for (int r = 0; r < 4; ++r)
        t[y + 8 * r][x] = W[(size_t)(k0 + y + 8 * r) * D + n0 + x];
    __syncthreads();
#pragma unroll
    for (int r = 0; r < 4; ++r) {
        float f = t[x][y + 8 * r];
        __nv_bfloat16 hb = __float2bfloat16_rn(f);
        __nv_bfloat16 lb = __float2bfloat16_rn(f - __bfloat162float(hb));
        size_t o = (size_t)(n0 + y + 8 * r) * D + k0 + x;
        hi[o] = hb;
        lo[o] = lb;
    }
}

/* ---------------- scores: content + skewed relative position ------------- */
__global__ __launch_bounds__(256) void scores_kernel(const float* __restrict__ rel_tab)
{
    __shared__ float qs[16][64];
    __shared__ float ks[16][64];
    __shared__ float rs[16][128];

    const int bh = blockIdx.y;
    const int b = bh / H, h = bh % H;

    int t = blockIdx.x, ti = 0;
    while (t >= ti + 1) { t -= ti + 1; ti++; }
    const int tj = t;
    const int i0 = ti * 64, j0 = tj * 64;
    const int lo = S - 64 - i0 + j0;

    const int tid = threadIdx.x;
    const int tx = tid & 15, ty = tid >> 4;
    const int q_li = tid >> 2,  q_dd = (tid & 3) << 2;
    const int r_li = tid >> 1,  r_dd = (tid & 1) << 3;
    const int base = 60 - 4 * ty + 4 * tx;

    const float* qb = g_q + (size_t)(b * S + i0) * D + h * HD;
    const float* kb = g_k + (size_t)(b * S + j0) * D + h * HD;
    const float* rb = rel_tab + h * HD;

    float acc[4][4];
#pragma unroll
    for (int a = 0; a < 4; a++)
#pragma unroll
        for (int c = 0; c < 4; c++) acc[a][c] = 0.f;

    for (int d0 = 0; d0 < HD; d0 += 16) {
        {
            float4 qv = *(const float4*)(qb + (size_t)q_li * D + d0 + q_dd);
            qs[q_dd + 0][q_li] = qv.x; qs[q_dd + 1][q_li] = qv.y;
            qs[q_dd + 2][q_li] = qv.z; qs[q_dd + 3][q_li] = qv.w;
            float4 kv = *(const float4*)(kb + (size_t)q_li * D + d0 + q_dd);
            ks[q_dd + 0][q_li] = kv.x; ks[q_dd + 1][q_li] = kv.y;
            ks[q_dd + 2][q_li] = kv.z; ks[q_dd + 3][q_li] = kv.w;
            int rrow = lo + r_li; if (rrow > S - 1) rrow = S - 1;
            const float* rp = rb + (size_t)rrow * D + d0 + r_dd;
            float4 r0v = *(const float4*)(rp);
            float4 r1v = *(const float4*)(rp + 4);
            rs[r_dd + 0][r_li] = r0v.x; rs[r_dd + 1][r_li] = r0v.y;
            rs[r_dd + 2][r_li] = r0v.z; rs[r_dd + 3][r_li] = r0v.w;
            rs[r_dd + 4][r_li] = r1v.x; rs[r_dd + 5][r_li] = r1v.y;
            rs[r_dd + 6][r_li] = r1v.z; rs[r_dd + 7][r_li] = r1v.w;
        }
        __syncthreads();
#pragma unroll
        for (int dd = 0; dd < 16; dd++) {
            float q4[4], k4[4], r8[8];
            *(float4*)(q4)     = *(const float4*)&qs[dd][4 * ty];
            *(float4*)(k4)     = *(const float4*)&ks[dd][4 * tx];
            *(float4*)(r8)     = *(const float4*)&rs[dd][base];
            *(float4*)(r8 + 4) = *(const float4*)&rs[dd][base + 4];
#pragma unroll
            for (int a = 0; a < 4; a++)
#pragma unroll
                for (int c = 0; c < 4; c++)
                    acc[a][c] = fmaf(q4[a], k4[c] + r8[3 - a + c], acc[a][c]);
        }
        __syncthreads();
    }

    float* outp = g_sc + (size_t)bh * S * S;
#pragma unroll
    for (int a = 0; a < 4; a++) {
        const int gi = i0 + 4 * ty + a;
        const int gj0 = j0 + 4 * tx;
        float4 o;
        o.x = (gj0 + 0 <= gi) ? acc[a][0] * SCALE : 0.f;
        o.y = (gj0 + 1 <= gi) ? acc[a][1] * SCALE : 0.f;
        o.z = (gj0 + 2 <= gi) ? acc[a][2] * SCALE : 0.f;
        o.w = (gj0 + 3 <= gi) ? acc[a][3] * SCALE : 0.f;
        *(float4*)(outp + (size_t)gi * S + gj0) = o;
    }
}

/* ---------------- causal row softmax (in place) --------------------------- */
__global__ __launch_bounds__(256) void softmax_kernel()
{
    const int row = blockIdx.x;
    const int i = row & (S - 1);
    float* base = g_sc + (size_t)row * S;
    const int tid = threadIdx.x;

    __shared__ float red[8];
    float v[4];
    float mx = -1e30f;
#pragma unroll
    for (int u = 0; u < 4; u++) {
        int j = tid + (u << 8);
        v[u] = (j <= i) ? base[j] : -1e30f;
        mx = fmaxf(mx, v[u]);
    }
#pragma unroll
    for (int o = 16; o > 0; o >>= 1)
        mx = fmaxf(mx, __shfl_xor_sync(0xffffffffu, mx, o));
    if ((tid & 31) == 0) red[tid >> 5] = mx;
    __syncthreads();
    float bm = red[0];
#pragma unroll
    for (int w = 1; w < 8; w++) bm = fmaxf(bm, red[w]);

    float sum = 0.f;
#pragma unroll
    for (int u = 0; u < 4; u++) {
        int j = tid + (u << 8);
        float e = (j <= i) ? __expf(v[u] - bm) : 0.f;
        v[u] = e;
        sum += e;
    }
#pragma unroll
    for (int o = 16; o > 0; o >>= 1)
        sum += __shfl_xor_sync(0xffffffffu, sum, o);
    __syncthreads();
    if ((tid & 31) == 0) red[tid >> 5] = sum;
    __syncthreads();
    float tot = 0.f;
#pragma unroll
    for (int w = 0; w < 8; w++) tot += red[w];
    const float inv = 1.f / tot;

#pragma unroll
    for (int u = 0; u < 4; u++) {
        int j = tid + (u << 8);
        if (j <= i) base[j] = v[u] * inv;
    }
}

/* ---------------- AV -------------------------------------------- */
__global__ __launch_bounds__(256) void av_kernel()
{
    __shared__ float ws[64][68];
    __shared__ float vs[64][68];

    const int bh = blockIdx.y;
    const int b = bh / H, h = bh % H;
    const int ti = blockIdx.x;
    const int i0 = ti * 64;
    const int tid = threadIdx.x;
    const int tx = tid & 15, ty = tid >> 4;
    const int lrow = tid >> 2, lc4 = (tid & 3) << 2;

    const float* wbase = g_sc + (size_t)bh * S * S;
    const float* vbase = g_v + (size_t)(b * S) * D + h * HD;

    float acc[4][4];
#pragma unroll
    for (int a = 0; a < 4; a++)
#pragma unroll
        for (int c = 0; c < 4; c++) acc[a][c] = 0.f;

    for (int jt = 0; jt <= ti; jt++) {
        const int j0 = jt * 64;
#pragma unroll
        for (int u = 0; u < 4; u++) {
            *(float4*)&ws[lrow][lc4 + 16 * u] =
                *(const float4*)(wbase + (size_t)(i0 + lrow) * S + j0 + lc4 + 16 * u);
            *(float4*)&vs[lrow][lc4 + 16 * u] =
                *(const float4*)(vbase + (size_t)(j0 + lrow) * D + lc4 + 16 * u);
        }
        __syncthreads();
#pragma unroll
        for (int lj = 0; lj < 64; lj++) {
            float wv[4];
#pragma unroll
            for (int a = 0; a < 4; a++) wv[a] = ws[4 * ty + a][lj];
            float4 v4 = *(const float4*)&vs[lj][4 * tx];
            const float vv[4] = { v4.x, v4.y, v4.z, v4.w };
#pragma unroll
            for (int a = 0; a < 4; a++)
#pragma unroll
                for (int c = 0; c < 4; c++)
                    acc[a][c] = fmaf(wv[a], vv[c], acc[a][c]);
        }
        __syncthreads();
    }

    float* outb = g_att + (size_t)(b * S + i0) * D + h * HD;
#pragma unroll
    for (int a = 0; a < 4; a++) {
        float4 o;
        o.x = acc[a][0]; o.y = acc[a][1]; o.z = acc[a][2]; o.w = acc[a][3];
        *(float4*)(outb + (size_t)(4 * ty + a) * D + 4 * tx) = o;
    }
}

/* ---------------- launcher ------------------------------------------------ */
extern "C" void kernel_launch(void* const* d_in, const int* in_sizes, int n_in,
                              void* d_out, int out_size)
{
    (void)in_sizes; (void)n_in; (void)out_size;
    const float* query = (const float*)d_in[0];
    const float* key   = (const float*)d_in[1];
    const float* value = (const float*)d_in[2];
    const float* Wq = (const float*)d_in[4];
    const float* bq = (const float*)d_in[5];
    const float* Wk = (const float*)d_in[6];
    const float* bk = (const float*)d_in[7];
    const float* Wv = (const float*)d_in[8];
    const float* bv = (const float*)d_in[9];
    const float* rel = (const float*)d_in[10];
    const float* Wo = (const float*)d_in[11];
    const float* bo = (const float*)d_in[12];

    float *qp, *kp, *vp, *ap;
    cudaGetSymbolAddress((void**)&qp, g_q);
    cudaGetSymbolAddress((void**)&kp, g_k);
    cudaGetSymbolAddress((void**)&vp, g_v);
    cudaGetSymbolAddress((void**)&ap, g_att);

    __nv_bfloat16 *ahi, *alo, *whi, *wlo;
    cudaGetSymbolAddress((void**)&ahi, s_ahi);
    cudaGetSymbolAddress((void**)&alo, s_alo);
    cudaGetSymbolAddress((void**)&whi, s_whi);
    cudaGetSymbolAddress((void**)&wlo, s_wlo);

    const dim3 gw(D / 32, D / 32), bw(32, 8);
    const dim3 gg(D / 128, M_TOT / 128);   /* (8, 32) */

    split_kernel<<<M_TOT * D / 1024, 256>>>(query, ahi, alo);
    wsplitT_kernel<<<gw, bw>>>(Wq, whi, wlo);
    gemm_mma<<<gg, 128>>>(ahi, alo, whi, wlo, bq, qp);

    split_kernel<<<M_TOT * D / 1024, 256>>>(key, ahi, alo);
    wsplitT_kernel<<<gw, bw>>>(Wk, whi, wlo);
    gemm_mma<<<gg, 128>>>(ahi, alo, whi, wlo, bk, kp);

    split_kernel<<<M_TOT * D / 1024, 256>>>(value, ahi, alo);
    wsplitT_kernel<<<gw, bw>>>(Wv, whi, wlo);
    gemm_mma<<<gg, 128>>>(ahi, alo, whi, wlo, bv, vp);

    scores_kernel<<<dim3(136, BB * H), 256>>>(rel);
    softmax_kernel<<<BB * H * S, 256>>>();
    av_kernel<<<dim3(S / 64, BB * H), 256>>>();

    split_kernel<<<M_TOT * D / 1024, 256>>>(ap, ahi, alo);
    wsplitT_kernel<<<gw, bw>>>(Wo, whi, wlo);
    gemm_mma<<<gg, 128>>>(ahi, alo, whi, wlo, bo, (float*)d_out);
}

// round 15
// speedup vs baseline: 1.7221x; 1.3692x over previous
#include <cuda_runtime.h>
#include <cuda_bf16.h>
#include <math.h>
#include <stdint.h>

#define BB    4
#define S     1024
#define D     1024
#define H     16
#define HD    64
#define M_TOT (BB * S)          /* 4096 */
#define SCALE 0.125f            /* 1/sqrt(64) */

/* ---------------- scratch (device globals; no allocation) ---------------- */
__device__ __align__(128) float g_q[M_TOT * D];                 /* 16 MB */
__device__ __align__(128) float g_k[M_TOT * D];                 /* 16 MB */
__device__ __align__(128) float g_v[M_TOT * D];                 /* 16 MB */
__device__ __align__(128) float g_att[M_TOT * D];               /* 16 MB */
__device__ __align__(128) float g_sc[(size_t)BB * H * S * S];   /* 256 MB (C / weights) */
__device__ __align__(128) float g_p[(size_t)BB * H * S * S];    /* 256 MB (P = Q R^T) */

/* bf16 split staging */
__device__ __align__(128) __nv_bfloat16 s_ahi[(size_t)M_TOT * D];  /* 8 MB */
__device__ __align__(128) __nv_bfloat16 s_alo[(size_t)M_TOT * D];  /* 8 MB */
__device__ __align__(128) __nv_bfloat16 s_whi[(size_t)D * D];      /* 2 MB (W^T) */
__device__ __align__(128) __nv_bfloat16 s_wlo[(size_t)D * D];      /* 2 MB (W^T) */
__device__ __align__(128) __nv_bfloat16 s_qhi[(size_t)M_TOT * D];  /* 8 MB */
__device__ __align__(128) __nv_bfloat16 s_qlo[(size_t)M_TOT * D];  /* 8 MB */
__device__ __align__(128) __nv_bfloat16 s_khi[(size_t)M_TOT * D];  /* 8 MB */
__device__ __align__(128) __nv_bfloat16 s_klo[(size_t)M_TOT * D];  /* 8 MB */
__device__ __align__(128) __nv_bfloat16 s_rhi[(size_t)D * D];      /* 2 MB */
__device__ __align__(128) __nv_bfloat16 s_rlo[(size_t)D * D];      /* 2 MB */

/* ---------------- common helpers ---------------- */
__device__ __forceinline__ uint32_t smem_u32(const void* p) {
    uint32_t a;
    asm("{ .reg .u64 t; cvta.to.shared.u64 t, %1; cvt.u32.u64 %0, t; }"
        : "=r"(a) : "l"(p));
    return a;
}
__device__ __forceinline__ void cp16(uint32_t dst, const void* src) {
    asm volatile("cp.async.cg.shared.global [%0], [%1], 16;"
                 :: "r"(dst), "l"(src) : "memory");
}
__device__ __forceinline__ void mma16816(float* d, uint32_t a0, uint32_t a1,
                                         uint32_t a2, uint32_t a3,
                                         uint32_t b0, uint32_t b1) {
    asm volatile(
        "mma.sync.aligned.m16n8k16.row.col.f32.bf16.bf16.f32 "
        "{%0,%1,%2,%3}, {%4,%5,%6,%7}, {%8,%9}, {%0,%1,%2,%3};"
        : "+f"(d[0]), "+f"(d[1]), "+f"(d[2]), "+f"(d[3])
        : "r"(a0), "r"(a1), "r"(a2), "r"(a3), "r"(b0), "r"(b1));
}

/* ============ mma.sync bf16 GEMM v2: C[M,1024] = A @ W + bias =============
   8 warps, CTA 128x128, warp tile 32x64, BK=32, cp.async double buffer.
   K_ext = 3072 via segments (Ah,Wh),(Al,Wh),(Ah,Wl). ---------------------- */
__global__ __launch_bounds__(256) void gemm_mma(
    const __nv_bfloat16* __restrict__ ahi, const __nv_bfloat16* __restrict__ alo,
    const __nv_bfloat16* __restrict__ whi, const __nv_bfloat16* __restrict__ wlo,
    const float* __restrict__ bias, float* __restrict__ C)
{
    __shared__ __align__(16) __nv_bfloat16 As[2][128][40];
    __shared__ __align__(16) __nv_bfloat16 Ws[2][128][40];

    const int tid = threadIdx.x;
    const int wid = tid >> 5, l = tid & 31;
    const int m0 = blockIdx.y * 128, n0 = blockIdx.x * 128;
    const int mw = (wid >> 1) * 32, nw = (wid & 1) * 64;
    const int r = l >> 2, kk = (l & 3) * 2;

    const __nv_bfloat16* const segA[3] = { ahi, alo, ahi };
    const __nv_bfloat16* const segW[3] = { whi, whi, wlo };

    float acc[2][8][4];
#pragma unroll
    for (int mt = 0; mt < 2; mt++)
#pragma unroll
        for (int nt = 0; nt < 8; nt++)
#pragma unroll
            for (int e = 0; e < 4; e++) acc[mt][nt][e] = 0.f;

    auto load_stage = [&](int c, int st) {
        const int seg = c >> 5;
        const int kc = (c & 31) << 5;
        const __nv_bfloat16* Ab = segA[seg];
        const __nv_bfloat16* Wb = segW[seg];
#pragma unroll
        for (int q = 0; q < 2; ++q) {
            const int cc = tid + q * 256;         /* 0..511 */
            const int row = cc >> 2, sg = (cc & 3) * 8;
            cp16(smem_u32(&As[st][row][sg]),
                 Ab + (size_t)(m0 + row) * 1024 + kc + sg);
            cp16(smem_u32(&Ws[st][row][sg]),
                 Wb + (size_t)(n0 + row) * 1024 + kc + sg);
        }
    };

    load_stage(0, 0);
    asm volatile("cp.async.commit_group;" ::: "memory");

    for (int c = 0; c < 96; ++c) {
        const int st = c & 1;
        if (c + 1 < 96) {
            load_stage(c + 1, st ^ 1);
            asm volatile("cp.async.commit_group;" ::: "memory");
            asm volatile("cp.async.wait_group 1;" ::: "memory");
        } else {
            asm volatile("cp.async.wait_group 0;" ::: "memory");
        }
        __syncthreads();

#pragma unroll
        for (int ko = 0; ko < 32; ko += 16) {
            uint32_t bb[8][2];
#pragma unroll
            for (int nt = 0; nt < 8; ++nt) {
                const int N8 = nw + nt * 8 + r;
                bb[nt][0] = *(const uint32_t*)&Ws[st][N8][kk + ko];
                bb[nt][1] = *(const uint32_t*)&Ws[st][N8][kk + ko + 8];
            }
#pragma unroll
            for (int mt = 0; mt < 2; ++mt) {
                const int row = mw + mt * 16 + r;
                uint32_t a0 = *(const uint32_t*)&As[st][row][kk + ko];
                uint32_t a1 = *(const uint32_t*)&As[st][row + 8][kk + ko];
                uint32_t a2 = *(const uint32_t*)&As[st][row][kk + ko + 8];
                uint32_t a3 = *(const uint32_t*)&As[st][row + 8][kk + ko + 8];
#pragma unroll
                for (int nt = 0; nt < 8; ++nt)
                    mma16816(acc[mt][nt], a0, a1, a2, a3, bb[nt][0], bb[nt][1]);
            }
        }
        __syncthreads();
    }

#pragma unroll
    for (int mt = 0; mt < 2; ++mt) {
        const int gm = m0 + mw + mt * 16 + r;
#pragma unroll
        for (int nt = 0; nt < 8; ++nt) {
            const int gn = n0 + nw + nt * 8 + kk;
            const float bx = bias[gn], by = bias[gn + 1];
            float2 o0 = { acc[mt][nt][0] + bx, acc[mt][nt][1] + by };
            float2 o1 = { acc[mt][nt][2] + bx, acc[mt][nt][3] + by };
            *(float2*)(C + (size_t)gm * 1024 + gn) = o0;
            *(float2*)(C + (size_t)(gm + 8) * 1024 + gn) = o1;
        }
    }
}

/* ============ scores via MMA: C = Q K^T (causal tiles) and ===============
   P[i,u] = Q R^T for u-tiles [7-ti, 7]. CTA = (i-strip of 128, bh).
   8 warps, warp tile 32x64, K=64, 3-way bf16 split products. ------------- */
__global__ __launch_bounds__(256) void qkp_kernel(
    const __nv_bfloat16* __restrict__ qhi, const __nv_bfloat16* __restrict__ qlo,
    const __nv_bfloat16* __restrict__ khi, const __nv_bfloat16* __restrict__ klo,
    const __nv_bfloat16* __restrict__ rhi, const __nv_bfloat16* __restrict__ rlo)
{
    extern __shared__ __nv_bfloat16 dsm[];
    typedef __nv_bfloat16 Row72[72];
    Row72* sQh = (Row72*)dsm;            /* [128][72] */
    Row72* sQl = sQh + 128;
    Row72* sBh = sQl + 128;              /* [2*128][72] */
    Row72* sBl = sBh + 256;

    const int ti = (S / 128 - 1) - blockIdx.x;  /* heavy strips first */
    const int bh = blockIdx.y;
    const int b = bh >> 4, h = bh & 15;
    const int i0 = ti * 128;

    const int tid = threadIdx.x;
    const int wid = tid >> 5, l = tid & 31;
    const int mw = (wid >> 1) * 32, nw = (wid & 1) * 64;
    const int r = l >> 2, kk = (l & 3) * 2;

    /* load Q tile (hi+lo): 2 mats x 128 rows x 8 segs = 2048 cp16 */
    {
        const size_t qoff = ((size_t)(b * S) + i0) * 1024 + h * 64;
#pragma unroll
        for (int q = 0; q < 8; ++q) {
            const int cc = tid + q * 256;        /* 0..2047 */
            const int mat = cc >> 10;
            const int c2 = cc & 1023;
            const int row = c2 >> 3, sg = (c2 & 7) * 8;
            const __nv_bfloat16* src = (mat ? qlo : qhi) + qoff +
                                       (size_t)row * 1024 + sg;
            cp16(smem_u32(&(mat ? sQl : sQh)[row][sg]), src);
        }
        asm volatile("cp.async.commit_group;" ::: "memory");
    }

    const int nC = ti + 1, L = 2 * nC;

    auto loadB = [&](int t, int st) {
        const int isC = (t < nC);
        const size_t base = isC
            ? ((size_t)(b * S) + t * 128) * 1024 + h * 64
            : ((size_t)((7 - ti + (t - nC)) * 128)) * 1024 + h * 64;
        const __nv_bfloat16* ph = isC ? khi : rhi;
        const __nv_bfloat16* pl = isC ? klo : rlo;
#pragma unroll
        for (int q = 0; q < 8; ++q) {
            const int cc = tid + q * 256;        /* 0..2047 */
            const int mat = cc >> 10;
            const int c2 = cc & 1023;
            const int row = c2 >> 3, sg = (c2 & 7) * 8;
            cp16(smem_u32(&(mat ? sBl : sBh)[st * 128 + row][sg]),
                 (mat ? pl : ph) + base + (size_t)row * 1024 + sg);
        }
    };

    loadB(0, 0);
    asm volatile("cp.async.commit_group;" ::: "memory");

    float acc[2][8][4];
#pragma unroll
    for (int mt = 0; mt < 2; mt++)
#pragma unroll
        for (int nt = 0; nt < 8; nt++)
#pragma unroll
            for (int e = 0; e < 4; e++) acc[mt][nt][e] = 0.f;

    for (int t = 0; t < L; ++t) {
        const int st = t & 1;
        if (t + 1 < L) {
            loadB(t + 1, st ^ 1);
            asm volatile("cp.async.commit_group;" ::: "memory");
            asm volatile("cp.async.wait_group 1;" ::: "memory");
        } else {
            asm volatile("cp.async.wait_group 0;" ::: "memory");
        }
        __syncthreads();

        Row72* Bh = sBh + st * 128;
        Row72* Bl = sBl + st * 128;
        Row72* Ap[3] = { sQh, sQl, sQh };
        Row72* Bp[3] = { Bh,  Bh,  Bl  };

#pragma unroll
        for (int p = 0; p < 3; ++p) {
            Row72* Af = Ap[p];
            Row72* Bf = Bp[p];
#pragma unroll
            for (int ko = 0; ko < 64; ko += 16) {
                uint32_t bb[8][2];
#pragma unroll
                for (int nt = 0; nt < 8; ++nt) {
                    const int N8 = nw + nt * 8 + r;
                    bb[nt][0] = *(const uint32_t*)&Bf[N8][kk + ko];
                    bb[nt][1] = *(const uint32_t*)&Bf[N8][kk + ko + 8];
                }
#pragma unroll
                for (int mt = 0; mt < 2; ++mt) {
                    const int row = mw + mt * 16 + r;
                    uint32_t a0 = *(const uint32_t*)&Af[row][kk + ko];
                    uint32_t a1 = *(const uint32_t*)&Af[row + 8][kk + ko];
                    uint32_t a2 = *(const uint32_t*)&Af[row][kk + ko + 8];
                    uint32_t a3 = *(const uint32_t*)&Af[row + 8][kk + ko + 8];
#pragma unroll
                    for (int nt = 0; nt < 8; ++nt)
                        mma16816(acc[mt][nt], a0, a1, a2, a3,
                                 bb[nt][0], bb[nt][1]);
                }
            }
        }

        /* epilogue for this output tile */
        {
            float* outp = (t < nC ? g_sc : g_p) + (size_t)bh * S * S;
            const int col0 = (t < nC ? t : (7 - ti + (t - nC))) * 128;
#pragma unroll
            for (int mt = 0; mt < 2; ++mt) {
                const int gm = i0 + mw + mt * 16 + r;
#pragma unroll
                for (int nt = 0; nt < 8; ++nt) {
                    const int gn = col0 + nw + nt * 8 + kk;
                    float2 o0 = { acc[mt][nt][0], acc[mt][nt][1] };
                    float2 o1 = { acc[mt][nt][2], acc[mt][nt][3] };
                    *(float2*)(outp + (size_t)gm * S + gn) = o0;
                    *(float2*)(outp + (size_t)(gm + 8) * S + gn) = o1;
#pragma unroll
                    for (int e = 0; e < 4; ++e) acc[mt][nt][e] = 0.f;
                }
            }
        }
        __syncthreads();
    }
}

/* ------------- fp32 -> bf16 hi/lo split (elementwise) -------------------- */
__global__ __launch_bounds__(256) void split_kernel(
    const float* __restrict__ src, __nv_bfloat16* __restrict__ hi,
    __nv_bfloat16* __restrict__ lo)
{
    const size_t i = (size_t)blockIdx.x * 256 + threadIdx.x; /* float4 index */
    float4 v = ((const float4*)src)[i];
    float f[4] = { v.x, v.y, v.z, v.w };
    uint32_t hw[2], lw[2];
#pragma unroll
    for (int p = 0; p < 2; ++p) {
        uint32_t h0 = 0, h1 = 0, l0 = 0, l1 = 0;
#pragma unroll
        for (int q = 0; q < 2; ++q) {
            float x = f[2 * p + q];
            __nv_bfloat16 hb = __float2bfloat16_rn(x);
            __nv_bfloat16 lb = __float2bfloat16_rn(x - __bfloat162float(hb));
            uint32_t hu = (uint32_t)__bfloat16_as_ushort(hb);
            uint32_t lu = (uint32_t)__bfloat16_as_ushort(lb);
            if (q == 0) { h0 = hu; l0 = lu; } else { h1 = hu; l1 = lu; }
        }
        hw[p] = h0 | (h1 << 16);
        lw[p] = l0 | (l1 << 16);
    }
    ((uint2*)hi)[i] = make_uint2(hw[0], hw[1]);
    ((uint2*)lo)[i] = make_uint2(lw[0], lw[1]);
}

/* ------------- W [K,N] -> W^T hi/lo bf16 [N,K] (transpose + split) -------- */
__global__ void wsplitT_kernel(const float* __restrict__ W,
                               __nv_bfloat16* __restrict__ hi,
                               __nv_bfloat16* __restrict__ lo)
{
    __shared__ float t[32][33];
    const int k0 = blockIdx.y * 32, n0 = blockIdx.x * 32;
    const int x = threadIdx.x, y = threadIdx.y;       /* 32 x 8 */
#pragma unroll
    for (int r = 0; r < 4; ++r)
        t[y + 8 * r][x] = W[(size_t)(k0 + y + 8 * r) * D + n0 + x];
    __syncthreads();
#pragma unroll
    for (int r = 0; r < 4; ++r) {
        float f = t[x][y + 8 * r];
        __nv_bfloat16 hb = __float2bfloat16_rn(f);
        __nv_bfloat16 lb = __float2bfloat16_rn(f - __bfloat162float(hb));
        size_t o = (size_t)(n0 + y + 8 * r) * D + k0 + x;
        hi[o] = hb;
        lo[o] = lb;
    }
}

/* ---------------- softmax2: combine C + shifted P, softmax, write row ---- */
__global__ __launch_bounds__(256) void softmax2_kernel()
{
    const int row = blockIdx.x;          /* bh*S + i */
    const int i = row & (S - 1);
    const int bh = row >> 10;
    float* base = g_sc + (size_t)row * S;
    const float* Pb = g_p + (size_t)bh * S * S + (size_t)i * S + (S - 1 - i);
    const int tid = threadIdx.x;

    __shared__ float red[8];
    float v[4];
    float mx = -1e30f;
#pragma unroll
    for (int u = 0; u < 4; u++) {
        int j = tid + (u << 8);
        float raw = (j <= i) ? (base[j] + Pb[j]) * SCALE : -1e30f;
        v[u] = raw;
        mx = fmaxf(mx, raw);
    }
#pragma unroll
    for (int o = 16; o > 0; o >>= 1)
        mx = fmaxf(mx, __shfl_xor_sync(0xffffffffu, mx, o));
    if ((tid & 31) == 0) red[tid >> 5] = mx;
    __syncthreads();
    float bm = red[0];
#pragma unroll
    for (int w = 1; w < 8; w++) bm = fmaxf(bm, red[w]);

    float sum = 0.f;
#pragma unroll
    for (int u = 0; u < 4; u++) {
        int j = tid + (u << 8);
        float e = (j <= i) ? __expf(v[u] - bm) : 0.f;
        v[u] = e;
        sum += e;
    }
#pragma unroll
    for (int o = 16; o > 0; o >>= 1)
        sum += __shfl_xor_sync(0xffffffffu, sum, o);
    __syncthreads();
    if ((tid & 31) == 0) red[tid >> 5] = sum;
    __syncthreads();
    float tot = 0.f;
#pragma unroll
    for (int w = 0; w < 8; w++) tot += red[w];
    const float inv = 1.f / tot;

#pragma unroll
    for (int u = 0; u < 4; u++) {
        int j = tid + (u << 8);
        base[j] = (j <= i) ? v[u] * inv : 0.f;
    }
}

/* ---------------- AV -------------------------------------------- */
__global__ __launch_bounds__(256) void av_kernel()
{
    __shared__ float ws[64][68];
    __shared__ float vs[64][68];

    const int bh = blockIdx.y;
    const int b = bh / H, h = bh % H;
    const int ti = blockIdx.x;
    const int i0 = ti * 64;
    const int tid = threadIdx.x;
    const int tx = tid & 15, ty = tid >> 4;
    const int lrow = tid >> 2, lc4 = (tid & 3) << 2;

    const float* wbase = g_sc + (size_t)bh * S * S;
    const float* vbase = g_v + (size_t)(b * S) * D + h * HD;

    float acc[4][4];
#pragma unroll
    for (int a = 0; a < 4; a++)
#pragma unroll
        for (int c = 0; c < 4; c++) acc[a][c] = 0.f;

    for (int jt = 0; jt <= ti; jt++) {
        const int j0 = jt * 64;
#pragma unroll
        for (int u = 0; u < 4; u++) {
            *(float4*)&ws[lrow][lc4 + 16 * u] =
                *(const float4*)(wbase + (size_t)(i0 + lrow) * S + j0 + lc4 + 16 * u);
            *(float4*)&vs[lrow][lc4 + 16 * u] =
                *(const float4*)(vbase + (size_t)(j0 + lrow) * D + lc4 + 16 * u);
        }
        __syncthreads();
#pragma unroll
        for (int lj = 0; lj < 64; lj++) {
            float wv[4];
#pragma unroll
            for (int a = 0; a < 4; a++) wv[a] = ws[4 * ty + a][lj];
            float4 v4 = *(const float4*)&vs[lj][4 * tx];
            const float vv[4] = { v4.x, v4.y, v4.z, v4.w };
#pragma unroll
            for (int a = 0; a < 4; a++)
#pragma unroll
                for (int c = 0; c < 4; c++)
                    acc[a][c] = fmaf(wv[a], vv[c], acc[a][c]);
        }
        __syncthreads();
    }

    float* outb = g_att + (size_t)(b * S + i0) * D + h * HD;
#pragma unroll
    for (int a = 0; a < 4; a++) {
        float4 o;
        o.x = acc[a][0]; o.y = acc[a][1]; o.z = acc[a][2]; o.w = acc[a][3];
        *(float4*)(outb + (size_t)(4 * ty + a) * D + 4 * tx) = o;
    }
}

/* ---------------- launcher ------------------------------------------------ */
extern "C" void kernel_launch(void* const* d_in, const int* in_sizes, int n_in,
                              void* d_out, int out_size)
{
    (void)in_sizes; (void)n_in; (void)out_size;
    const float* query = (const float*)d_in[0];
    const float* key   = (const float*)d_in[1];
    const float* value = (const float*)d_in[2];
    const float* Wq = (const float*)d_in[4];
    const float* bq = (const float*)d_in[5];
    const float* Wk = (const float*)d_in[6];
    const float* bk = (const float*)d_in[7];
    const float* Wv = (const float*)d_in[8];
    const float* bv = (const float*)d_in[9];
    const float* rel = (const float*)d_in[10];
    const float* Wo = (const float*)d_in[11];
    const float* bo = (const float*)d_in[12];

    float *qp, *kp, *vp, *ap;
    cudaGetSymbolAddress((void**)&qp, g_q);
    cudaGetSymbolAddress((void**)&kp, g_k);
    cudaGetSymbolAddress((void**)&vp, g_v);
    cudaGetSymbolAddress((void**)&ap, g_att);

    __nv_bfloat16 *ahi, *alo, *whi, *wlo, *qhi, *qlo, *khi, *klo, *rhi, *rlo;
    cudaGetSymbolAddress((void**)&ahi, s_ahi);
    cudaGetSymbolAddress((void**)&alo, s_alo);
    cudaGetSymbolAddress((void**)&whi, s_whi);
    cudaGetSymbolAddress((void**)&wlo, s_wlo);
    cudaGetSymbolAddress((void**)&qhi, s_qhi);
    cudaGetSymbolAddress((void**)&qlo, s_qlo);
    cudaGetSymbolAddress((void**)&khi, s_khi);
    cudaGetSymbolAddress((void**)&klo, s_klo);
    cudaGetSymbolAddress((void**)&rhi, s_rhi);
    cudaGetSymbolAddress((void**)&rlo, s_rlo);

    const dim3 gw(D / 32, D / 32), bw(32, 8);
    const dim3 gg(D / 128, M_TOT / 128);   /* (8, 32) */

    const int QKP_SMEM = 768 * 72 * 2;     /* 110592 B */
    cudaFuncSetAttribute(qkp_kernel, cudaFuncAttributeMaxDynamicSharedMemorySize,
                         QKP_SMEM);

    /* projections */
    split_kernel<<<M_TOT * D / 1024, 256>>>(query, ahi, alo);
    wsplitT_kernel<<<gw, bw>>>(Wq, whi, wlo);
    gemm_mma<<<gg, 256>>>(ahi, alo, whi, wlo, bq, qp);

    split_kernel<<<M_TOT * D / 1024, 256>>>(key, ahi, alo);
    wsplitT_kernel<<<gw, bw>>>(Wk, whi, wlo);
    gemm_mma<<<gg, 256>>>(ahi, alo, whi, wlo, bk, kp);

    split_kernel<<<M_TOT * D / 1024, 256>>>(value, ahi, alo);
    wsplitT_kernel<<<gw, bw>>>(Wv, whi, wlo);
    gemm_mma<<<gg, 256>>>(ahi, alo, whi, wlo, bv, vp);

    /* attention: splits, C&P GEMMs, fused skew-softmax, AV */
    split_kernel<<<M_TOT * D / 1024, 256>>>(qp, qhi, qlo);
    split_kernel<<<M_TOT * D / 1024, 256>>>(kp, khi, klo);
    split_kernel<<<D * D / 1024, 256>>>(rel, rhi, rlo);

    qkp_kernel<<<dim3(S / 128, BB * H), 256, QKP_SMEM>>>(qhi, qlo, khi, klo,
                                                         rhi, rlo);
    softmax2_kernel<<<BB * H * S, 256>>>();
    av_kernel<<<dim3(S / 64, BB * H), 256>>>();

    /* output projection */
    split_kernel<<<M_TOT * D / 1024, 256>>>(ap, ahi, alo);
    wsplitT_kernel<<<gw, bw>>>(Wo, whi, wlo);
    gemm_mma<<<gg, 256>>>(ahi, alo, whi, wlo, bo, (float*)d_out);
}

// round 16
// speedup vs baseline: 1.7764x; 1.0315x over previous
#include <cuda_runtime.h>
#include <cuda_bf16.h>
#include <math.h>
#include <stdint.h>

#define BB    4
#define S     1024
#define D     1024
#define H     16
#define HD    64
#define M_TOT (BB * S)          /* 4096 */
#define SCALE 0.125f            /* 1/sqrt(64) */

/* ---------------- scratch (device globals; no allocation) ---------------- */
__device__ __align__(128) float g_v[M_TOT * D];                 /* 16 MB */
__device__ __align__(128) float g_att[M_TOT * D];               /* 16 MB */
__device__ __align__(128) float g_sc[(size_t)BB * H * S * S];   /* 256 MB (C / weights) */
__device__ __align__(128) float g_p[(size_t)BB * H * S * S];    /* 256 MB (P = Q R^T) */

/* bf16 split staging */
__device__ __align__(128) __nv_bfloat16 s_ahi[(size_t)M_TOT * D];  /* 8 MB */
__device__ __align__(128) __nv_bfloat16 s_alo[(size_t)M_TOT * D];  /* 8 MB */
__device__ __align__(128) __nv_bfloat16 s_whi[(size_t)D * D];      /* 2 MB (W^T) */
__device__ __align__(128) __nv_bfloat16 s_wlo[(size_t)D * D];      /* 2 MB (W^T) */
__device__ __align__(128) __nv_bfloat16 s_qhi[(size_t)M_TOT * D];  /* 8 MB */
__device__ __align__(128) __nv_bfloat16 s_qlo[(size_t)M_TOT * D];  /* 8 MB */
__device__ __align__(128) __nv_bfloat16 s_khi[(size_t)M_TOT * D];  /* 8 MB */
__device__ __align__(128) __nv_bfloat16 s_klo[(size_t)M_TOT * D];  /* 8 MB */
__device__ __align__(128) __nv_bfloat16 s_rhi[(size_t)D * D];      /* 2 MB */
__device__ __align__(128) __nv_bfloat16 s_rlo[(size_t)D * D];      /* 2 MB */

/* ---------------- common helpers ---------------- */
__device__ __forceinline__ uint32_t smem_u32(const void* p) {
    uint32_t a;
    asm("{ .reg .u64 t; cvta.to.shared.u64 t, %1; cvt.u32.u64 %0, t; }"
        : "=r"(a) : "l"(p));
    return a;
}
__device__ __forceinline__ void cp16(uint32_t dst, const void* src) {
    asm volatile("cp.async.cg.shared.global [%0], [%1], 16;"
                 :: "r"(dst), "l"(src) : "memory");
}
__device__ __forceinline__ void mma16816(float* d, uint32_t a0, uint32_t a1,
                                         uint32_t a2, uint32_t a3,
                                         uint32_t b0, uint32_t b1) {
    asm volatile(
        "mma.sync.aligned.m16n8k16.row.col.f32.bf16.bf16.f32 "
        "{%0,%1,%2,%3}, {%4,%5,%6,%7}, {%8,%9}, {%0,%1,%2,%3};"
        : "+f"(d[0]), "+f"(d[1]), "+f"(d[2]), "+f"(d[3])
        : "r"(a0), "r"(a1), "r"(a2), "r"(a3), "r"(b0), "r"(b1));
}
__device__ __forceinline__ void ldm4(uint32_t* r, uint32_t addr) {
    asm volatile("ldmatrix.sync.aligned.m8n8.x4.shared.b16 {%0,%1,%2,%3}, [%4];"
                 : "=r"(r[0]), "=r"(r[1]), "=r"(r[2]), "=r"(r[3]) : "r"(addr));
}

/* ============ mma.sync bf16 GEMM v3 (ldmatrix): =========================
   C[M,1024] = A @ W + bias. 8 warps, CTA 128x128, warp tile 32x64, BK=32,
   cp.async double buffer. K_ext = 3072 via (Ah,Wh),(Al,Wh),(Ah,Wl).
   If ohi != nullptr, epilogue writes bf16 hi/lo split instead of fp32 C. */
__global__ __launch_bounds__(256) void gemm_mma(
    const __nv_bfloat16* __restrict__ ahi, const __nv_bfloat16* __restrict__ alo,
    const __nv_bfloat16* __restrict__ whi, const __nv_bfloat16* __restrict__ wlo,
    const float* __restrict__ bias, float* __restrict__ C,
    __nv_bfloat16* __restrict__ ohi, __nv_bfloat16* __restrict__ olo)
{
    __shared__ __align__(16) __nv_bfloat16 As[2][128][40];
    __shared__ __align__(16) __nv_bfloat16 Ws[2][128][40];

    const int tid = threadIdx.x;
    const int wid = tid >> 5, l = tid & 31;
    const int m0 = blockIdx.y * 128, n0 = blockIdx.x * 128;
    const int mw = (wid >> 1) * 32, nw = (wid & 1) * 64;
    const int r = l >> 2, kk = (l & 3) * 2;
    const int jr = l & 7, qd = l >> 3;

    const __nv_bfloat16* const segA[3] = { ahi, alo, ahi };
    const __nv_bfloat16* const segW[3] = { whi, whi, wlo };

    float acc[2][8][4];
#pragma unroll
    for (int mt = 0; mt < 2; mt++)
#pragma unroll
        for (int nt = 0; nt < 8; nt++)
#pragma unroll
            for (int e = 0; e < 4; e++) acc[mt][nt][e] = 0.f;

    auto load_stage = [&](int c, int st) {
        const int seg = c >> 5;
        const int kc = (c & 31) << 5;
        const __nv_bfloat16* Ab = segA[seg];
        const __nv_bfloat16* Wb = segW[seg];
#pragma unroll
        for (int q = 0; q < 2; ++q) {
            const int cc = tid + q * 256;         /* 0..511 */
            const int row = cc >> 2, sg = (cc & 3) * 8;
            cp16(smem_u32(&As[st][row][sg]),
                 Ab + (size_t)(m0 + row) * 1024 + kc + sg);
            cp16(smem_u32(&Ws[st][row][sg]),
                 Wb + (size_t)(n0 + row) * 1024 + kc + sg);
        }
    };

    load_stage(0, 0);
    asm volatile("cp.async.commit_group;" ::: "memory");

    for (int c = 0; c < 96; ++c) {
        const int st = c & 1;
        if (c + 1 < 96) {
            load_stage(c + 1, st ^ 1);
            asm volatile("cp.async.commit_group;" ::: "memory");
            asm volatile("cp.async.wait_group 1;" ::: "memory");
        } else {
            asm volatile("cp.async.wait_group 0;" ::: "memory");
        }
        __syncthreads();

#pragma unroll
        for (int ko = 0; ko < 32; ko += 16) {
            uint32_t bb[8][2];
#pragma unroll
            for (int p = 0; p < 4; ++p) {
                uint32_t rr[4];
                ldm4(rr, smem_u32(&Ws[st][nw + p * 16 + (qd >> 1) * 8 + jr]
                                        [ko + (qd & 1) * 8]));
                bb[2 * p][0] = rr[0]; bb[2 * p][1] = rr[1];
                bb[2 * p + 1][0] = rr[2]; bb[2 * p + 1][1] = rr[3];
            }
#pragma unroll
            for (int mt = 0; mt < 2; ++mt) {
                uint32_t aa[4];
                ldm4(aa, smem_u32(&As[st][mw + mt * 16 + jr + (qd & 1) * 8]
                                        [ko + (qd >> 1) * 8]));
#pragma unroll
                for (int nt = 0; nt < 8; ++nt)
                    mma16816(acc[mt][nt], aa[0], aa[1], aa[2], aa[3],
                             bb[nt][0], bb[nt][1]);
            }
        }
        __syncthreads();
    }

    if (ohi) {
#pragma unroll
        for (int mt = 0; mt < 2; ++mt) {
            const int gm = m0 + mw + mt * 16 + r;
#pragma unroll
            for (int nt = 0; nt < 8; ++nt) {
                const int gn = n0 + nw + nt * 8 + kk;
                const float bx = bias[gn], by = bias[gn + 1];
#pragma unroll
                for (int hrow = 0; hrow < 2; ++hrow) {
                    float x0 = acc[mt][nt][2 * hrow + 0] + bx;
                    float x1 = acc[mt][nt][2 * hrow + 1] + by;
                    __nv_bfloat16 h0 = __float2bfloat16_rn(x0);
                    __nv_bfloat16 h1 = __float2bfloat16_rn(x1);
                    __nv_bfloat16 l0 = __float2bfloat16_rn(x0 - __bfloat162float(h0));
                    __nv_bfloat16 l1 = __float2bfloat16_rn(x1 - __bfloat162float(h1));
                    const size_t off = (size_t)(gm + 8 * hrow) * 1024 + gn;
                    uint32_t hw = (uint32_t)__bfloat16_as_ushort(h0) |
                                  ((uint32_t)__bfloat16_as_ushort(h1) << 16);
                    uint32_t lw = (uint32_t)__bfloat16_as_ushort(l0) |
                                  ((uint32_t)__bfloat16_as_ushort(l1) << 16);
                    *(uint32_t*)(ohi + off) = hw;
                    *(uint32_t*)(olo + off) = lw;
                }
            }
        }
    } else {
#pragma unroll
        for (int mt = 0; mt < 2; ++mt) {
            const int gm = m0 + mw + mt * 16 + r;
#pragma unroll
            for (int nt = 0; nt < 8; ++nt) {
                const int gn = n0 + nw + nt * 8 + kk;
                const float bx = bias[gn], by = bias[gn + 1];
                float2 o0 = { acc[mt][nt][0] + bx, acc[mt][nt][1] + by };
                float2 o1 = { acc[mt][nt][2] + bx, acc[mt][nt][3] + by };
                *(float2*)(C + (size_t)gm * 1024 + gn) = o0;
                *(float2*)(C + (size_t)(gm + 8) * 1024 + gn) = o1;
            }
        }
    }
}

/* ============ scores via MMA (ldmatrix): C = Q K^T causal tiles, =========
   P = Q R^T for u-tiles [7-ti, 7]. CTA = (i-strip of 128, bh). ----------- */
__global__ __launch_bounds__(256) void qkp_kernel(
    const __nv_bfloat16* __restrict__ qhi, const __nv_bfloat16* __restrict__ qlo,
    const __nv_bfloat16* __restrict__ khi, const __nv_bfloat16* __restrict__ klo,
    const __nv_bfloat16* __restrict__ rhi, const __nv_bfloat16* __restrict__ rlo)
{
    extern __shared__ __nv_bfloat16 dsm[];
    typedef __nv_bfloat16 Row72[72];
    Row72* sQh = (Row72*)dsm;            /* [128][72] */
    Row72* sQl = sQh + 128;
    Row72* sBh = sQl + 128;              /* [2*128][72] */
    Row72* sBl = sBh + 256;

    const int ti = (S / 128 - 1) - blockIdx.x;  /* heavy strips first */
    const int bh = blockIdx.y;
    const int b = bh >> 4, h = bh & 15;
    const int i0 = ti * 128;

    const int tid = threadIdx.x;
    const int wid = tid >> 5, l = tid & 31;
    const int mw = (wid >> 1) * 32, nw = (wid & 1) * 64;
    const int r = l >> 2, kk = (l & 3) * 2;
    const int jr = l & 7, qd = l >> 3;

    /* load Q tile (hi+lo): 2 mats x 128 rows x 8 segs = 2048 cp16 */
    {
        const size_t qoff = ((size_t)(b * S) + i0) * 1024 + h * 64;
#pragma unroll
        for (int q = 0; q < 8; ++q) {
            const int cc = tid + q * 256;        /* 0..2047 */
            const int mat = cc >> 10;
            const int c2 = cc & 1023;
            const int row = c2 >> 3, sg = (c2 & 7) * 8;
            const __nv_bfloat16* src = (mat ? qlo : qhi) + qoff +
                                       (size_t)row * 1024 + sg;
            cp16(smem_u32(&(mat ? sQl : sQh)[row][sg]), src);
        }
        asm volatile("cp.async.commit_group;" ::: "memory");
    }

    const int nC = ti + 1, L = 2 * nC;

    auto loadB = [&](int t, int st) {
        const int isC = (t < nC);
        const size_t base = isC
            ? ((size_t)(b * S) + t * 128) * 1024 + h * 64
            : ((size_t)((7 - ti + (t - nC)) * 128)) * 1024 + h * 64;
        const __nv_bfloat16* ph = isC ? khi : rhi;
        const __nv_bfloat16* pl = isC ? klo : rlo;
#pragma unroll
        for (int q = 0; q < 8; ++q) {
            const int cc = tid + q * 256;        /* 0..2047 */
            const int mat = cc >> 10;
            const int c2 = cc & 1023;
            const int row = c2 >> 3, sg = (c2 & 7) * 8;
            cp16(smem_u32(&(mat ? sBl : sBh)[st * 128 + row][sg]),
                 (mat ? pl : ph) + base + (size_t)row * 1024 + sg);
        }
    };

    loadB(0, 0);
    asm volatile("cp.async.commit_group;" ::: "memory");

    float acc[2][8][4];
#pragma unroll
    for (int mt = 0; mt < 2; mt++)
#pragma unroll
        for (int nt = 0; nt < 8; nt++)
#pragma unroll
            for (int e = 0; e < 4; e++) acc[mt][nt][e] = 0.f;

    for (int t = 0; t < L; ++t) {
        const int st = t & 1;
        if (t + 1 < L) {
            loadB(t + 1, st ^ 1);
            asm volatile("cp.async.commit_group;" ::: "memory");
            asm volatile("cp.async.wait_group 1;" ::: "memory");
        } else {
            asm volatile("cp.async.wait_group 0;" ::: "memory");
        }
        __syncthreads();

        Row72* Bh = sBh + st * 128;
        Row72* Bl = sBl + st * 128;
        Row72* Ap[3] = { sQh, sQl, sQh };
        Row72* Bp[3] = { Bh,  Bh,  Bl  };

#pragma unroll
        for (int p = 0; p < 3; ++p) {
            Row72* Af = Ap[p];
            Row72* Bf = Bp[p];
#pragma unroll
            for (int ko = 0; ko < 64; ko += 16) {
                uint32_t bb[8][2];
#pragma unroll
                for (int pp = 0; pp < 4; ++pp) {
                    uint32_t rr[4];
                    ldm4(rr, smem_u32(&Bf[nw + pp * 16 + (qd >> 1) * 8 + jr]
                                         [ko + (qd & 1) * 8]));
                    bb[2 * pp][0] = rr[0]; bb[2 * pp][1] = rr[1];
                    bb[2 * pp + 1][0] = rr[2]; bb[2 * pp + 1][1] = rr[3];
                }
#pragma unroll
                for (int mt = 0; mt < 2; ++mt) {
                    uint32_t aa[4];
                    ldm4(aa, smem_u32(&Af[mw + mt * 16 + jr + (qd & 1) * 8]
                                         [ko + (qd >> 1) * 8]));
#pragma unroll
                    for (int nt = 0; nt < 8; ++nt)
                        mma16816(acc[mt][nt], aa[0], aa[1], aa[2], aa[3],
                                 bb[nt][0], bb[nt][1]);
                }
            }
        }

        /* epilogue for this output tile */
        {
            float* outp = (t < nC ? g_sc : g_p) + (size_t)bh * S * S;
            const int col0 = (t < nC ? t : (7 - ti + (t - nC))) * 128;
#pragma unroll
            for (int mt = 0; mt < 2; ++mt) {
                const int gm = i0 + mw + mt * 16 + r;
#pragma unroll
                for (int nt = 0; nt < 8; ++nt) {
                    const int gn = col0 + nw + nt * 8 + kk;
                    float2 o0 = { acc[mt][nt][0], acc[mt][nt][1] };
                    float2 o1 = { acc[mt][nt][2], acc[mt][nt][3] };
                    *(float2*)(outp + (size_t)gm * S + gn) = o0;
                    *(float2*)(outp + (size_t)(gm + 8) * S + gn) = o1;
#pragma unroll
                    for (int e = 0; e < 4; ++e) acc[mt][nt][e] = 0.f;
                }
            }
        }
        __syncthreads();
    }
}

/* ------------- fp32 -> bf16 hi/lo split (elementwise) -------------------- */
__global__ __launch_bounds__(256) void split_kernel(
    const float* __restrict__ src, __nv_bfloat16* __restrict__ hi,
    __nv_bfloat16* __restrict__ lo)
{
    const size_t i = (size_t)blockIdx.x * 256 + threadIdx.x; /* float4 index */
    float4 v = ((const float4*)src)[i];
    float f[4] = { v.x, v.y, v.z, v.w };
    uint32_t hw[2], lw[2];
#pragma unroll
    for (int p = 0; p < 2; ++p) {
        uint32_t h0 = 0, h1 = 0, l0 = 0, l1 = 0;
#pragma unroll
        for (int q = 0; q < 2; ++q) {
            float x = f[2 * p + q];
            __nv_bfloat16 hb = __float2bfloat16_rn(x);
            __nv_bfloat16 lb = __float2bfloat16_rn(x - __bfloat162float(hb));
            uint32_t hu = (uint32_t)__bfloat16_as_ushort(hb);
            uint32_t lu = (uint32_t)__bfloat16_as_ushort(lb);
            if (q == 0) { h0 = hu; l0 = lu; } else { h1 = hu; l1 = lu; }
        }
        hw[p] = h0 | (h1 << 16);
        lw[p] = l0 | (l1 << 16);
    }
    ((uint2*)hi)[i] = make_uint2(hw[0], hw[1]);
    ((uint2*)lo)[i] = make_uint2(lw[0], lw[1]);
}

/* ------------- W [K,N] -> W^T hi/lo bf16 [N,K] (transpose + split) -------- */
__global__ void wsplitT_kernel(const float* __restrict__ W,
                               __nv_bfloat16* __restrict__ hi,
                               __nv_bfloat16* __restrict__ lo)
{
    __shared__ float t[32][33];
    const int k0 = blockIdx.y * 32, n0 = blockIdx.x * 32;
    const int x = threadIdx.x, y = threadIdx.y;       /* 32 x 8 */
#pragma unroll
    for (int r = 0; r < 4; ++r)
        t[y + 8 * r][x] = W[(size_t)(k0 + y + 8 * r) * D + n0 + x];
    __syncthreads();
#pragma unroll
    for (int r = 0; r < 4; ++r) {
        float f = t[x][y + 8 * r];
        __nv_bfloat16 hb = __float2bfloat16_rn(f);
        __nv_bfloat16 lb = __float2bfloat16_rn(f - __bfloat162float(hb));
        size_t o = (size_t)(n0 + y + 8 * r) * D + k0 + x;
        hi[o] = hb;
        lo[o] = lb;
    }
}

/* ---------------- softmax2: combine C + shifted P, softmax, write row ---- */
__global__ __launch_bounds__(256) void softmax2_kernel()
{
    const int row = blockIdx.x;          /* bh*S + i */
    const int i = row & (S - 1);
    const int bh = row >> 10;
    float* base = g_sc + (size_t)row * S;
    const float* Pb = g_p + (size_t)bh * S * S + (size_t)i * S + (S - 1 - i);
    const int tid = threadIdx.x;

    __shared__ float red[8];
    float v[4];
    float mx = -1e30f;
#pragma unroll
    for (int u = 0; u < 4; u++) {
        int j = tid + (u << 8);
        float raw = (j <= i) ? (base[j] + Pb[j]) * SCALE : -1e30f;
        v[u] = raw;
        mx = fmaxf(mx, raw);
    }
#pragma unroll
    for (int o = 16; o > 0; o >>= 1)
        mx = fmaxf(mx, __shfl_xor_sync(0xffffffffu, mx, o));
    if ((tid & 31) == 0) red[tid >> 5] = mx;
    __syncthreads();
    float bm = red[0];
#pragma unroll
    for (int w = 1; w < 8; w++) bm = fmaxf(bm, red[w]);

    float sum = 0.f;
#pragma unroll
    for (int u = 0; u < 4; u++) {
        int j = tid + (u << 8);
        float e = (j <= i) ? __expf(v[u] - bm) : 0.f;
        v[u] = e;
        sum += e;
    }
#pragma unroll
    for (int o = 16; o > 0; o >>= 1)
        sum += __shfl_xor_sync(0xffffffffu, sum, o);
    __syncthreads();
    if ((tid & 31) == 0) red[tid >> 5] = sum;
    __syncthreads();
    float tot = 0.f;
#pragma unroll
    for (int w = 0; w < 8; w++) tot += red[w];
    const float inv = 1.f / tot;

#pragma unroll
    for (int u = 0; u < 4; u++) {
        int j = tid + (u << 8);
        base[j] = (j <= i) ? v[u] * inv : 0.f;
    }
}

/* ---------------- AV -------------------------------------------- */
__global__ __launch_bounds__(256) void av_kernel()
{
    __shared__ float ws[64][68];
    __shared__ float vs[64][68];

    const int bh = blockIdx.y;
    const int b = bh / H, h = bh % H;
    const int ti = blockIdx.x;
    const int i0 = ti * 64;
    const int tid = threadIdx.x;
    const int tx = tid & 15, ty = tid >> 4;
    const int lrow = tid >> 2, lc4 = (tid & 3) << 2;

    const float* wbase = g_sc + (size_t)bh * S * S;
    const float* vbase = g_v + (size_t)(b * S) * D + h * HD;

    float acc[4][4];
#pragma unroll
    for (int a = 0; a < 4; a++)
#pragma unroll
        for (int c = 0; c < 4; c++) acc[a][c] = 0.f;

    for (int jt = 0; jt <= ti; jt++) {
        const int j0 = jt * 64;
#pragma unroll
        for (int u = 0; u < 4; u++) {
            *(float4*)&ws[lrow][lc4 + 16 * u] =
                *(const float4*)(wbase + (size_t)(i0 + lrow) * S + j0 + lc4 + 16 * u);
            *(float4*)&vs[lrow][lc4 + 16 * u] =
                *(const float4*)(vbase + (size_t)(j0 + lrow) * D + lc4 + 16 * u);
        }
        __syncthreads();
#pragma unroll
        for (int lj = 0; lj < 64; lj++) {
            float wv[4];
#pragma unroll
            for (int a = 0; a < 4; a++) wv[a] = ws[4 * ty + a][lj];
            float4 v4 = *(const float4*)&vs[lj][4 * tx];
            const float vv[4] = { v4.x, v4.y, v4.z, v4.w };
#pragma unroll
            for (int a = 0; a < 4; a++)
#pragma unroll
                for (int c = 0; c < 4; c++)
                    acc[a][c] = fmaf(wv[a], vv[c], acc[a][c]);
        }
        __syncthreads();
    }

    float* outb = g_att + (size_t)(b * S + i0) * D + h * HD;
#pragma unroll
    for (int a = 0; a < 4; a++) {
        float4 o;
        o.x = acc[a][0]; o.y = acc[a][1]; o.z = acc[a][2]; o.w = acc[a][3];
        *(float4*)(outb + (size_t)(4 * ty + a) * D + 4 * tx) = o;
    }
}

/* ---------------- launcher ------------------------------------------------ */
extern "C" void kernel_launch(void* const* d_in, const int* in_sizes, int n_in,
                              void* d_out, int out_size)
{
    (void)in_sizes; (void)n_in; (void)out_size;
    const float* query = (const float*)d_in[0];
    const float* key   = (const float*)d_in[1];
    const float* value = (const float*)d_in[2];
    const float* Wq = (const float*)d_in[4];
    const float* bq = (const float*)d_in[5];
    const float* Wk = (const float*)d_in[6];
    const float* bk = (const float*)d_in[7];
    const float* Wv = (const float*)d_in[8];
    const float* bv = (const float*)d_in[9];
    const float* rel = (const float*)d_in[10];
    const float* Wo = (const float*)d_in[11];
    const float* bo = (const float*)d_in[12];

    float *vp, *ap;
    cudaGetSymbolAddress((void**)&vp, g_v);
    cudaGetSymbolAddress((void**)&ap, g_att);

    __nv_bfloat16 *ahi, *alo, *whi, *wlo, *qhi, *qlo, *khi, *klo, *rhi, *rlo;
    cudaGetSymbolAddress((void**)&ahi, s_ahi);
    cudaGetSymbolAddress((void**)&alo, s_alo);
    cudaGetSymbolAddress((void**)&whi, s_whi);
    cudaGetSymbolAddress((void**)&wlo, s_wlo);
    cudaGetSymbolAddress((void**)&qhi, s_qhi);
    cudaGetSymbolAddress((void**)&qlo, s_qlo);
    cudaGetSymbolAddress((void**)&khi, s_khi);
    cudaGetSymbolAddress((void**)&klo, s_klo);
    cudaGetSymbolAddress((void**)&rhi, s_rhi);
    cudaGetSymbolAddress((void**)&rlo, s_rlo);

    const dim3 gw(D / 32, D / 32), bw(32, 8);
    const dim3 gg(D / 128, M_TOT / 128);   /* (8, 32) */

    const int QKP_SMEM = 768 * 72 * 2;     /* 110592 B */
    cudaFuncSetAttribute(qkp_kernel, cudaFuncAttributeMaxDynamicSharedMemorySize,
                         QKP_SMEM);

    /* projections: Q and K write bf16 hi/lo split directly */
    split_kernel<<<M_TOT * D / 1024, 256>>>(query, ahi, alo);
    wsplitT_kernel<<<gw, bw>>>(Wq, whi, wlo);
    gemm_mma<<<gg, 256>>>(ahi, alo, whi, wlo, bq, nullptr, qhi, qlo);

    split_kernel<<<M_TOT * D / 1024, 256>>>(key, ahi, alo);
    wsplitT_kernel<<<gw, bw>>>(Wk, whi, wlo);
    gemm_mma<<<gg, 256>>>(ahi, alo, whi, wlo, bk, nullptr, khi, klo);

    split_kernel<<<M_TOT * D / 1024, 256>>>(value, ahi, alo);
    wsplitT_kernel<<<gw, bw>>>(Wv, whi, wlo);
    gemm_mma<<<gg, 256>>>(ahi, alo, whi, wlo, bv, vp, nullptr, nullptr);

    /* attention */
    split_kernel<<<D * D / 1024, 256>>>(rel, rhi, rlo);
    qkp_kernel<<<dim3(S / 128, BB * H), 256, QKP_SMEM>>>(qhi, qlo, khi, klo,
                                                         rhi, rlo);
    softmax2_kernel<<<BB * H * S, 256>>>();
    av_kernel<<<dim3(S / 64, BB * H), 256>>>();

    /* output projection */
    split_kernel<<<M_TOT * D / 1024, 256>>>(ap, ahi, alo);
    wsplitT_kernel<<<gw, bw>>>(Wo, whi, wlo);
    gemm_mma<<<gg, 256>>>(ahi, alo, whi, wlo, bo, (float*)d_out,
                          nullptr, nullptr);
}

// round 17
// speedup vs baseline: 1.9821x; 1.1158x over previous
#include <cuda_runtime.h>
#include <cuda_bf16.h>
#include <math.h>
#include <stdint.h>

#define BB    4
#define S     1024
#define D     1024
#define H     16
#define HD    64
#define M_TOT (BB * S)          /* 4096 */
#define SCALE 0.125f            /* 1/sqrt(64) */

/* ---------------- scratch (device globals; no allocation) ---------------- */
__device__ __align__(128) float g_p[(size_t)BB * H * S * S];    /* 256 MB (P = Q R^T) */

/* bf16 split staging */
__device__ __align__(128) __nv_bfloat16 s_ahi[(size_t)M_TOT * D];  /* 8 MB */
__device__ __align__(128) __nv_bfloat16 s_alo[(size_t)M_TOT * D];  /* 8 MB */
__device__ __align__(128) __nv_bfloat16 s_whi[(size_t)D * D];      /* 2 MB (W^T) */
__device__ __align__(128) __nv_bfloat16 s_wlo[(size_t)D * D];      /* 2 MB (W^T) */
__device__ __align__(128) __nv_bfloat16 s_qhi[(size_t)M_TOT * D];  /* 8 MB */
__device__ __align__(128) __nv_bfloat16 s_qlo[(size_t)M_TOT * D];  /* 8 MB */
__device__ __align__(128) __nv_bfloat16 s_khi[(size_t)M_TOT * D];  /* 8 MB */
__device__ __align__(128) __nv_bfloat16 s_klo[(size_t)M_TOT * D];  /* 8 MB */
__device__ __align__(128) __nv_bfloat16 s_vhi[(size_t)M_TOT * D];  /* 8 MB */
__device__ __align__(128) __nv_bfloat16 s_vlo[(size_t)M_TOT * D];  /* 8 MB */
__device__ __align__(128) __nv_bfloat16 s_rhi[(size_t)D * D];      /* 2 MB */
__device__ __align__(128) __nv_bfloat16 s_rlo[(size_t)D * D];      /* 2 MB */

/* ---------------- common helpers ---------------- */
__device__ __forceinline__ uint32_t smem_u32(const void* p) {
    uint32_t a;
    asm("{ .reg .u64 t; cvta.to.shared.u64 t, %1; cvt.u32.u64 %0, t; }"
        : "=r"(a) : "l"(p));
    return a;
}
__device__ __forceinline__ void cp16(uint32_t dst, const void* src) {
    asm volatile("cp.async.cg.shared.global [%0], [%1], 16;"
                 :: "r"(dst), "l"(src) : "memory");
}
__device__ __forceinline__ void mma16816(float* d, uint32_t a0, uint32_t a1,
                                         uint32_t a2, uint32_t a3,
                                         uint32_t b0, uint32_t b1) {
    asm volatile(
        "mma.sync.aligned.m16n8k16.row.col.f32.bf16.bf16.f32 "
        "{%0,%1,%2,%3}, {%4,%5,%6,%7}, {%8,%9}, {%0,%1,%2,%3};"
        : "+f"(d[0]), "+f"(d[1]), "+f"(d[2]), "+f"(d[3])
        : "r"(a0), "r"(a1), "r"(a2), "r"(a3), "r"(b0), "r"(b1));
}
__device__ __forceinline__ void ldm4(uint32_t* r, uint32_t addr) {
    asm volatile("ldmatrix.sync.aligned.m8n8.x4.shared.b16 {%0,%1,%2,%3}, [%4];"
                 : "=r"(r[0]), "=r"(r[1]), "=r"(r[2]), "=r"(r[3]) : "r"(addr));
}
__device__ __forceinline__ void ldm4t(uint32_t* r, uint32_t addr) {
    asm volatile("ldmatrix.sync.aligned.m8n8.x4.trans.shared.b16 {%0,%1,%2,%3}, [%4];"
                 : "=r"(r[0]), "=r"(r[1]), "=r"(r[2]), "=r"(r[3]) : "r"(addr));
}
/* split pair of fp32 into packed bf16 hi-word / lo-word */
__device__ __forceinline__ void split2(float x, float y, uint32_t& hw, uint32_t& lw) {
    __nv_bfloat16 hx = __float2bfloat16_rn(x);
    __nv_bfloat16 hy = __float2bfloat16_rn(y);
    __nv_bfloat16 lx = __float2bfloat16_rn(x - __bfloat162float(hx));
    __nv_bfloat16 ly = __float2bfloat16_rn(y - __bfloat162float(hy));
    hw = (uint32_t)__bfloat16_as_ushort(hx) | ((uint32_t)__bfloat16_as_ushort(hy) << 16);
    lw = (uint32_t)__bfloat16_as_ushort(lx) | ((uint32_t)__bfloat16_as_ushort(ly) << 16);
}

/* ============ mma.sync bf16 GEMM (ldmatrix): ==============================
   C[M,1024] = A @ W + bias. 8 warps, CTA 128x128, warp tile 32x64, BK=32,
   cp.async double buffer. K_ext = 3072 via (Ah,Wh),(Al,Wh),(Ah,Wl).
   If ohi != nullptr, epilogue writes bf16 hi/lo split instead of fp32 C. */
__global__ __launch_bounds__(256) void gemm_mma(
    const __nv_bfloat16* __restrict__ ahi, const __nv_bfloat16* __restrict__ alo,
    const __nv_bfloat16* __restrict__ whi, const __nv_bfloat16* __restrict__ wlo,
    const float* __restrict__ bias, float* __restrict__ C,
    __nv_bfloat16* __restrict__ ohi, __nv_bfloat16* __restrict__ olo)
{
    __shared__ __align__(16) __nv_bfloat16 As[2][128][40];
    __shared__ __align__(16) __nv_bfloat16 Ws[2][128][40];

    const int tid = threadIdx.x;
    const int wid = tid >> 5, l = tid & 31;
    const int m0 = blockIdx.y * 128, n0 = blockIdx.x * 128;
    const int mw = (wid >> 1) * 32, nw = (wid & 1) * 64;
    const int r = l >> 2, kk = (l & 3) * 2;
    const int jr = l & 7, qd = l >> 3;

    const __nv_bfloat16* const segA[3] = { ahi, alo, ahi };
    const __nv_bfloat16* const segW[3] = { whi, whi, wlo };

    float acc[2][8][4];
#pragma unroll
    for (int mt = 0; mt < 2; mt++)
#pragma unroll
        for (int nt = 0; nt < 8; nt++)
#pragma unroll
            for (int e = 0; e < 4; e++) acc[mt][nt][e] = 0.f;

    auto load_stage = [&](int c, int st) {
        const int seg = c >> 5;
        const int kc = (c & 31) << 5;
        const __nv_bfloat16* Ab = segA[seg];
        const __nv_bfloat16* Wb = segW[seg];
#pragma unroll
        for (int q = 0; q < 2; ++q) {
            const int cc = tid + q * 256;         /* 0..511 */
            const int row = cc >> 2, sg = (cc & 3) * 8;
            cp16(smem_u32(&As[st][row][sg]),
                 Ab + (size_t)(m0 + row) * 1024 + kc + sg);
            cp16(smem_u32(&Ws[st][row][sg]),
                 Wb + (size_t)(n0 + row) * 1024 + kc + sg);
        }
    };

    load_stage(0, 0);
    asm volatile("cp.async.commit_group;" ::: "memory");

    for (int c = 0; c < 96; ++c) {
        const int st = c & 1;
        if (c + 1 < 96) {
            load_stage(c + 1, st ^ 1);
            asm volatile("cp.async.commit_group;" ::: "memory");
            asm volatile("cp.async.wait_group 1;" ::: "memory");
        } else {
            asm volatile("cp.async.wait_group 0;" ::: "memory");
        }
        __syncthreads();

#pragma unroll
        for (int ko = 0; ko < 32; ko += 16) {
            uint32_t bb[8][2];
#pragma unroll
            for (int p = 0; p < 4; ++p) {
                uint32_t rr[4];
                ldm4(rr, smem_u32(&Ws[st][nw + p * 16 + (qd >> 1) * 8 + jr]
                                        [ko + (qd & 1) * 8]));
                bb[2 * p][0] = rr[0]; bb[2 * p][1] = rr[1];
                bb[2 * p + 1][0] = rr[2]; bb[2 * p + 1][1] = rr[3];
            }
#pragma unroll
            for (int mt = 0; mt < 2; ++mt) {
                uint32_t aa[4];
                ldm4(aa, smem_u32(&As[st][mw + mt * 16 + jr + (qd & 1) * 8]
                                        [ko + (qd >> 1) * 8]));
#pragma unroll
                for (int nt = 0; nt < 8; ++nt)
                    mma16816(acc[mt][nt], aa[0], aa[1], aa[2], aa[3],
                             bb[nt][0], bb[nt][1]);
            }
        }
        __syncthreads();
    }

    if (ohi) {
#pragma unroll
        for (int mt = 0; mt < 2; ++mt) {
            const int gm = m0 + mw + mt * 16 + r;
#pragma unroll
            for (int nt = 0; nt < 8; ++nt) {
                const int gn = n0 + nw + nt * 8 + kk;
                const float bx = bias[gn], by = bias[gn + 1];
#pragma unroll
                for (int hrow = 0; hrow < 2; ++hrow) {
                    uint32_t hw, lw;
                    split2(acc[mt][nt][2 * hrow + 0] + bx,
                           acc[mt][nt][2 * hrow + 1] + by, hw, lw);
                    const size_t off = (size_t)(gm + 8 * hrow) * 1024 + gn;
                    *(uint32_t*)(ohi + off) = hw;
                    *(uint32_t*)(olo + off) = lw;
                }
            }
        }
    } else {
#pragma unroll
        for (int mt = 0; mt < 2; ++mt) {
            const int gm = m0 + mw + mt * 16 + r;
#pragma unroll
            for (int nt = 0; nt < 8; ++nt) {
                const int gn = n0 + nw + nt * 8 + kk;
                const float bx = bias[gn], by = bias[gn + 1];
                float2 o0 = { acc[mt][nt][0] + bx, acc[mt][nt][1] + by };
                float2 o1 = { acc[mt][nt][2] + bx, acc[mt][nt][3] + by };
                *(float2*)(C + (size_t)gm * 1024 + gn) = o0;
                *(float2*)(C + (size_t)(gm + 8) * 1024 + gn) = o1;
            }
        }
    }
}

/* ============ P = Q R^T for u-tiles [7-ti, 7] per 128-row strip ========== */
__global__ __launch_bounds__(256) void pqr_kernel(
    const __nv_bfloat16* __restrict__ qhi, const __nv_bfloat16* __restrict__ qlo,
    const __nv_bfloat16* __restrict__ rhi, const __nv_bfloat16* __restrict__ rlo)
{
    extern __shared__ __nv_bfloat16 dsm[];
    typedef __nv_bfloat16 Row72[72];
    Row72* sQh = (Row72*)dsm;            /* [128][72] */
    Row72* sQl = sQh + 128;
    Row72* sBh = sQl + 128;              /* [2*128][72] */
    Row72* sBl = sBh + 256;

    const int ti = (S / 128 - 1) - blockIdx.x;
    const int bh = blockIdx.y;
    const int b = bh >> 4, h = bh & 15;
    const int i0 = ti * 128;

    const int tid = threadIdx.x;
    const int wid = tid >> 5, l = tid & 31;
    const int mw = (wid >> 1) * 32, nw = (wid & 1) * 64;
    const int r = l >> 2, kk = (l & 3) * 2;
    const int jr = l & 7, qd = l >> 3;

    {
        const size_t qoff = ((size_t)(b * S) + i0) * 1024 + h * 64;
#pragma unroll
        for (int q = 0; q < 8; ++q) {
            const int cc = tid + q * 256;
            const int mat = cc >> 10;
            const int c2 = cc & 1023;
            const int row = c2 >> 3, sg = (c2 & 7) * 8;
            cp16(smem_u32(&(mat ? sQl : sQh)[row][sg]),
                 (mat ? qlo : qhi) + qoff + (size_t)row * 1024 + sg);
        }
        asm volatile("cp.async.commit_group;" ::: "memory");
    }

    const int L = ti + 1;

    auto loadB = [&](int t, int st) {
        const size_t base = (size_t)((7 - ti + t) * 128) * 1024 + h * 64;
#pragma unroll
        for (int q = 0; q < 8; ++q) {
            const int cc = tid + q * 256;
            const int mat = cc >> 10;
            const int c2 = cc & 1023;
            const int row = c2 >> 3, sg = (c2 & 7) * 8;
            cp16(smem_u32(&(mat ? sBl : sBh)[st * 128 + row][sg]),
                 (mat ? rlo : rhi) + base + (size_t)row * 1024 + sg);
        }
    };

    loadB(0, 0);
    asm volatile("cp.async.commit_group;" ::: "memory");

    float acc[2][8][4];
#pragma unroll
    for (int mt = 0; mt < 2; mt++)
#pragma unroll
        for (int nt = 0; nt < 8; nt++)
#pragma unroll
            for (int e = 0; e < 4; e++) acc[mt][nt][e] = 0.f;

    for (int t = 0; t < L; ++t) {
        const int st = t & 1;
        if (t + 1 < L) {
            loadB(t + 1, st ^ 1);
            asm volatile("cp.async.commit_group;" ::: "memory");
            asm volatile("cp.async.wait_group 1;" ::: "memory");
        } else {
            asm volatile("cp.async.wait_group 0;" ::: "memory");
        }
        __syncthreads();

        Row72* Bh = sBh + st * 128;
        Row72* Bl = sBl + st * 128;
        Row72* Ap[3] = { sQh, sQl, sQh };
        Row72* Bp[3] = { Bh,  Bh,  Bl  };

#pragma unroll
        for (int p = 0; p < 3; ++p) {
            Row72* Af = Ap[p];
            Row72* Bf = Bp[p];
#pragma unroll
            for (int ko = 0; ko < 64; ko += 16) {
                uint32_t bb[8][2];
#pragma unroll
                for (int pp = 0; pp < 4; ++pp) {
                    uint32_t rr[4];
                    ldm4(rr, smem_u32(&Bf[nw + pp * 16 + (qd >> 1) * 8 + jr]
                                         [ko + (qd & 1) * 8]));
                    bb[2 * pp][0] = rr[0]; bb[2 * pp][1] = rr[1];
                    bb[2 * pp + 1][0] = rr[2]; bb[2 * pp + 1][1] = rr[3];
                }
#pragma unroll
                for (int mt = 0; mt < 2; ++mt) {
                    uint32_t aa[4];
                    ldm4(aa, smem_u32(&Af[mw + mt * 16 + jr + (qd & 1) * 8]
                                         [ko + (qd >> 1) * 8]));
#pragma unroll
                    for (int nt = 0; nt < 8; ++nt)
                        mma16816(acc[mt][nt], aa[0], aa[1], aa[2], aa[3],
                                 bb[nt][0], bb[nt][1]);
                }
            }
        }

        {
            float* outp = g_p + (size_t)bh * S * S;
            const int col0 = (7 - ti + t) * 128;
#pragma unroll
            for (int mt = 0; mt < 2; ++mt) {
                const int gm = i0 + mw + mt * 16 + r;
#pragma unroll
                for (int nt = 0; nt < 8; ++nt) {
                    const int gn = col0 + nw + nt * 8 + kk;
                    float2 o0 = { acc[mt][nt][0], acc[mt][nt][1] };
                    float2 o1 = { acc[mt][nt][2], acc[mt][nt][3] };
                    *(float2*)(outp + (size_t)gm * S + gn) = o0;
                    *(float2*)(outp + (size_t)(gm + 8) * S + gn) = o1;
#pragma unroll
                    for (int e = 0; e < 4; ++e) acc[mt][nt][e] = 0.f;
                }
            }
        }
        __syncthreads();
    }
}

/* ============ fused flash attention with skewed relative positions ========
   CTA = (i-strip of 128 rows, bh). 8 warps, warp = 16 m rows x full n.
   Per j-tile: C = Q K^T (3 split products), add gathered P[i,1023-i+j],
   scale+mask, online softmax, O += W V (3 split products, W from regs).
   Epilogue writes O bf16 hi/lo split. ------------------------------------ */
__global__ __launch_bounds__(256) void fused_attn(
    const __nv_bfloat16* __restrict__ qhi, const __nv_bfloat16* __restrict__ qlo,
    const __nv_bfloat16* __restrict__ khi, const __nv_bfloat16* __restrict__ klo,
    const __nv_bfloat16* __restrict__ vhi, const __nv_bfloat16* __restrict__ vlo,
    __nv_bfloat16* __restrict__ ohi, __nv_bfloat16* __restrict__ olo)
{
    extern __shared__ __nv_bfloat16 dsm[];
    typedef __nv_bfloat16 Row72[72];
    Row72* sQh = (Row72*)dsm;        /* [128] */
    Row72* sQl = sQh + 128;
    Row72* sKh = sQl + 128;          /* [2][128] */
    Row72* sKl = sKh + 256;
    Row72* sVh = sKl + 256;          /* [2][128] */
    Row72* sVl = sVh + 256;

    const int ti = (S / 128 - 1) - blockIdx.x;   /* heavy strips first */
    const int bh = blockIdx.y;
    const int b = bh >> 4, h = bh & 15;
    const int i0 = ti * 128;

    const int tid = threadIdx.x;
    const int w = tid >> 5, l = tid & 31;
    const int mw = w * 16;
    const int gr = l >> 2, kk = (l & 3) * 2;
    const int jr = l & 7, qd = l >> 3;

    /* Q tile load */
    {
        const size_t qoff = ((size_t)(b * S) + i0) * 1024 + h * 64;
#pragma unroll
        for (int q = 0; q < 8; ++q) {
            const int cc = tid + q * 256;
            const int mat = cc >> 10;
            const int c2 = cc & 1023;
            const int row = c2 >> 3, sg = (c2 & 7) * 8;
            cp16(smem_u32(&(mat ? sQl : sQh)[row][sg]),
                 (mat ? qlo : qhi) + qoff + (size_t)row * 1024 + sg);
        }
        asm volatile("cp.async.commit_group;" ::: "memory");
    }

    auto loadKV = [&](int jt, int st) {
        const size_t base = ((size_t)(b * S) + jt * 128) * 1024 + h * 64;
        const __nv_bfloat16* const src[4] = { khi, klo, vhi, vlo };
#pragma unroll
        for (int q = 0; q < 16; ++q) {
            const int cc = tid + q * 256;        /* 0..4095 */
            const int mat = cc >> 10;            /* 0..3 */
            const int c2 = cc & 1023;
            const int row = c2 >> 3, sg = (c2 & 7) * 8;
            Row72* dst = (mat == 0 ? sKh : mat == 1 ? sKl : mat == 2 ? sVh : sVl);
            cp16(smem_u32(&dst[st * 128 + row][sg]),
                 src[mat] + base + (size_t)row * 1024 + sg);
        }
    };

    loadKV(0, 0);
    asm volatile("cp.async.commit_group;" ::: "memory");

    const int ii0 = i0 + mw + gr;       /* absolute row (0..1023) of e0/e1 */
    const int ii1 = ii0 + 8;
    const float* __restrict__ P0 = g_p + ((size_t)bh * S + ii0) * S;
    const float* __restrict__ P1 = P0 + (size_t)8 * S;

    float o[8][4];
#pragma unroll
    for (int no = 0; no < 8; ++no)
#pragma unroll
        for (int e = 0; e < 4; ++e) o[no][e] = 0.f;
    float m0 = -1e30f, m1 = -1e30f, s0 = 0.f, s1 = 0.f;

    const int L = ti + 1;
    for (int jt = 0; jt < L; ++jt) {
        const int st = jt & 1;
        if (jt + 1 < L) {
            loadKV(jt + 1, st ^ 1);
            asm volatile("cp.async.commit_group;" ::: "memory");
            asm volatile("cp.async.wait_group 1;" ::: "memory");
        } else {
            asm volatile("cp.async.wait_group 0;" ::: "memory");
        }
        __syncthreads();

        /* ---- C = Q K^T, 3 split products ---- */
        float c[16][4];
#pragma unroll
        for (int nt = 0; nt < 16; ++nt)
#pragma unroll
            for (int e = 0; e < 4; ++e) c[nt][e] = 0.f;

        Row72* Kh = sKh + st * 128;
        Row72* Kl = sKl + st * 128;
#pragma unroll
        for (int ko = 0; ko < 64; ko += 16) {
            uint32_t bb[16][2];
#pragma unroll
            for (int p4 = 0; p4 < 8; ++p4) {
                uint32_t rr[4];
                ldm4(rr, smem_u32(&Kh[p4 * 16 + (qd >> 1) * 8 + jr]
                                     [ko + (qd & 1) * 8]));
                bb[2 * p4][0] = rr[0]; bb[2 * p4][1] = rr[1];
                bb[2 * p4 + 1][0] = rr[2]; bb[2 * p4 + 1][1] = rr[3];
            }
            uint32_t ah[4], al[4];
            ldm4(ah, smem_u32(&sQh[mw + jr + (qd & 1) * 8][ko + (qd >> 1) * 8]));
            ldm4(al, smem_u32(&sQl[mw + jr + (qd & 1) * 8][ko + (qd >> 1) * 8]));
#pragma unroll
            for (int nt = 0; nt < 16; ++nt)
                mma16816(c[nt], ah[0], ah[1], ah[2], ah[3], bb[nt][0], bb[nt][1]);
#pragma unroll
            for (int nt = 0; nt < 16; ++nt)
                mma16816(c[nt], al[0], al[1], al[2], al[3], bb[nt][0], bb[nt][1]);
#pragma unroll
            for (int p4 = 0; p4 < 8; ++p4) {
                uint32_t rr[4];
                ldm4(rr, smem_u32(&Kl[p4 * 16 + (qd >> 1) * 8 + jr]
                                     [ko + (qd & 1) * 8]));
                bb[2 * p4][0] = rr[0]; bb[2 * p4][1] = rr[1];
                bb[2 * p4 + 1][0] = rr[2]; bb[2 * p4 + 1][1] = rr[3];
            }
#pragma unroll
            for (int nt = 0; nt < 16; ++nt)
                mma16816(c[nt], ah[0], ah[1], ah[2], ah[3], bb[nt][0], bb[nt][1]);
        }

        /* ---- add skewed P, scale, mask ---- */
        const int jb = jt * 128;
#pragma unroll
        for (int nt = 0; nt < 16; ++nt) {
            const int gn = jb + nt * 8 + kk;
            const int u0 = 1023 - ii0 + gn;
            const int u1 = 1023 - ii1 + gn;
            c[nt][0] = (c[nt][0] + P0[u0 > 1023 ? 1023 : u0]) * SCALE;
            c[nt][1] = (c[nt][1] + P0[u0 + 1 > 1023 ? 1023 : u0 + 1]) * SCALE;
            c[nt][2] = (c[nt][2] + P1[u1 > 1023 ? 1023 : u1]) * SCALE;
            c[nt][3] = (c[nt][3] + P1[u1 + 1 > 1023 ? 1023 : u1 + 1]) * SCALE;
            if (jt == ti) {
                if (gn > ii0)     c[nt][0] = -1e30f;
                if (gn + 1 > ii0) c[nt][1] = -1e30f;
                if (gn > ii1)     c[nt][2] = -1e30f;
                if (gn + 1 > ii1) c[nt][3] = -1e30f;
            }
        }

        /* ---- online softmax ---- */
        float mx0 = -1e30f, mx1 = -1e30f;
#pragma unroll
        for (int nt = 0; nt < 16; ++nt) {
            mx0 = fmaxf(mx0, fmaxf(c[nt][0], c[nt][1]));
            mx1 = fmaxf(mx1, fmaxf(c[nt][2], c[nt][3]));
        }
        mx0 = fmaxf(mx0, __shfl_xor_sync(0xffffffffu, mx0, 1));
        mx0 = fmaxf(mx0, __shfl_xor_sync(0xffffffffu, mx0, 2));
        mx1 = fmaxf(mx1, __shfl_xor_sync(0xffffffffu, mx1, 1));
        mx1 = fmaxf(mx1, __shfl_xor_sync(0xffffffffu, mx1, 2));
        const float mn0 = fmaxf(m0, mx0), mn1 = fmaxf(m1, mx1);
        const float al0 = __expf(m0 - mn0), al1 = __expf(m1 - mn1);
        m0 = mn0; m1 = mn1;

        float sum0 = 0.f, sum1 = 0.f;
#pragma unroll
        for (int nt = 0; nt < 16; ++nt) {
            c[nt][0] = __expf(c[nt][0] - mn0); sum0 += c[nt][0];
            c[nt][1] = __expf(c[nt][1] - mn0); sum0 += c[nt][1];
            c[nt][2] = __expf(c[nt][2] - mn1); sum1 += c[nt][2];
            c[nt][3] = __expf(c[nt][3] - mn1); sum1 += c[nt][3];
        }
        sum0 += __shfl_xor_sync(0xffffffffu, sum0, 1);
        sum0 += __shfl_xor_sync(0xffffffffu, sum0, 2);
        sum1 += __shfl_xor_sync(0xffffffffu, sum1, 1);
        sum1 += __shfl_xor_sync(0xffffffffu, sum1, 2);
        s0 = s0 * al0 + sum0;
        s1 = s1 * al1 + sum1;
#pragma unroll
        for (int no = 0; no < 8; ++no) {
            o[no][0] *= al0; o[no][1] *= al0;
            o[no][2] *= al1; o[no][3] *= al1;
        }

        /* ---- O += W V (weights from C fragments, hi/lo split) ---- */
        Row72* Vh = sVh + st * 128;
        Row72* Vl = sVl + st * 128;
#pragma unroll
        for (int ks = 0; ks < 8; ++ks) {
            uint32_t wh[4], wl[4];
            split2(c[2 * ks][0],     c[2 * ks][1],     wh[0], wl[0]);
            split2(c[2 * ks][2],     c[2 * ks][3],     wh[1], wl[1]);
            split2(c[2 * ks + 1][0], c[2 * ks + 1][1], wh[2], wl[2]);
            split2(c[2 * ks + 1][2], c[2 * ks + 1][3], wh[3], wl[3]);
#pragma unroll
            for (int nb = 0; nb < 4; ++nb) {
                uint32_t rh[4], rl[4];
                ldm4t(rh, smem_u32(&Vh[ks * 16 + (qd & 1) * 8 + jr]
                                      [nb * 16 + (qd >> 1) * 8]));
                ldm4t(rl, smem_u32(&Vl[ks * 16 + (qd & 1) * 8 + jr]
                                      [nb * 16 + (qd >> 1) * 8]));
                mma16816(o[2 * nb],     wh[0], wh[1], wh[2], wh[3], rh[0], rh[1]);
                mma16816(o[2 * nb + 1], wh[0], wh[1], wh[2], wh[3], rh[2], rh[3]);
                mma16816(o[2 * nb],     wl[0], wl[1], wl[2], wl[3], rh[0], rh[1]);
                mma16816(o[2 * nb + 1], wl[0], wl[1], wl[2], wl[3], rh[2], rh[3]);
                mma16816(o[2 * nb],     wh[0], wh[1], wh[2], wh[3], rl[0], rl[1]);
                mma16816(o[2 * nb + 1], wh[0], wh[1], wh[2], wh[3], rl[2], rl[3]);
            }
        }
        __syncthreads();
    }

    /* ---- epilogue: normalize, split, store ---- */
    const float inv0 = 1.f / s0, inv1 = 1.f / s1;
    const size_t row0 = (size_t)(b * S) + ii0;
    const size_t row1 = row0 + 8;
#pragma unroll
    for (int no = 0; no < 8; ++no) {
        const int d0 = h * 64 + no * 8 + kk;
        uint32_t hw, lw;
        split2(o[no][0] * inv0, o[no][1] * inv0, hw, lw);
        *(uint32_t*)(ohi + row0 * 1024 + d0) = hw;
        *(uint32_t*)(olo + row0 * 1024 + d0) = lw;
        split2(o[no][2] * inv1, o[no][3] * inv1, hw, lw);
        *(uint32_t*)(ohi + row1 * 1024 + d0) = hw;
        *(uint32_t*)(olo + row1 * 1024 + d0) = lw;
    }
}

/* ------------- fp32 -> bf16 hi/lo split (elementwise) -------------------- */
__global__ __launch_bounds__(256) void split_kernel(
    const float* __restrict__ src, __nv_bfloat16* __restrict__ hi,
    __nv_bfloat16* __restrict__ lo)
{
    const size_t i = (size_t)blockIdx.x * 256 + threadIdx.x; /* float4 index */
    float4 v = ((const float4*)src)[i];
    uint32_t hw0, lw0, hw1, lw1;
    split2(v.x, v.y, hw0, lw0);
    split2(v.z, v.w, hw1, lw1);
    ((uint2*)hi)[i] = make_uint2(hw0, hw1);
    ((uint2*)lo)[i] = make_uint2(lw0, lw1);
}

/* ------------- W [K,N] -> W^T hi/lo bf16 [N,K] (transpose + split) -------- */
__global__ void wsplitT_kernel(const float* __restrict__ W,
                               __nv_bfloat16* __restrict__ hi,
                               __nv_bfloat16* __restrict__ lo)
{
    __shared__ float t[32][33];
    const int k0 = blockIdx.y * 32, n0 = blockIdx.x * 32;
    const int x = threadIdx.x, y = threadIdx.y;       /* 32 x 8 */
#pragma unroll
    for (int r = 0; r < 4; ++r)
        t[y + 8 * r][x] = W[(size_t)(k0 + y + 8 * r) * D + n0 + x];
    __syncthreads();
#pragma unroll
    for (int r = 0; r < 4; ++r) {
        float f = t[x][y + 8 * r];
        __nv_bfloat16 hb = __float2bfloat16_rn(f);
        __nv_bfloat16 lb = __float2bfloat16_rn(f - __bfloat162float(hb));
        size_t o = (size_t)(n0 + y + 8 * r) * D + k0 + x;
        hi[o] = hb;
        lo[o] = lb;
    }
}

/* ---------------- launcher ------------------------------------------------ */
extern "C" void kernel_launch(void* const* d_in, const int* in_sizes, int n_in,
                              void* d_out, int out_size)
{
    (void)in_sizes; (void)n_in; (void)out_size;
    const float* query = (const float*)d_in[0];
    const float* key   = (const float*)d_in[1];
    const float* value = (const float*)d_in[2];
    const float* Wq = (const float*)d_in[4];
    const float* bq = (const float*)d_in[5];
    const float* Wk = (const float*)d_in[6];
    const float* bk = (const float*)d_in[7];
    const float* Wv = (const float*)d_in[8];
    const float* bv = (const float*)d_in[9];
    const float* rel = (const float*)d_in[10];
    const float* Wo = (const float*)d_in[11];
    const float* bo = (const float*)d_in[12];

    __nv_bfloat16 *ahi, *alo, *whi, *wlo, *qhi, *qlo, *khi, *klo, *vhi, *vlo,
                  *rhi, *rlo;
    cudaGetSymbolAddress((void**)&ahi, s_ahi);
    cudaGetSymbolAddress((void**)&alo, s_alo);
    cudaGetSymbolAddress((void**)&whi, s_whi);
    cudaGetSymbolAddress((void**)&wlo, s_wlo);
    cudaGetSymbolAddress((void**)&qhi, s_qhi);
    cudaGetSymbolAddress((void**)&qlo, s_qlo);
    cudaGetSymbolAddress((void**)&khi, s_khi);
    cudaGetSymbolAddress((void**)&klo, s_klo);
    cudaGetSymbolAddress((void**)&vhi, s_vhi);
    cudaGetSymbolAddress((void**)&vlo, s_vlo);
    cudaGetSymbolAddress((void**)&rhi, s_rhi);
    cudaGetSymbolAddress((void**)&rlo, s_rlo);

    const dim3 gw(D / 32, D / 32), bw(32, 8);
    const dim3 gg(D / 128, M_TOT / 128);   /* (8, 32) */

    const int PQR_SMEM = 768 * 72 * 2;     /* 110592 B */
    cudaFuncSetAttribute(pqr_kernel, cudaFuncAttributeMaxDynamicSharedMemorySize,
                         PQR_SMEM);
    const int FA_SMEM = 1280 * 72 * 2;     /* 184320 B */
    cudaFuncSetAttribute(fused_attn, cudaFuncAttributeMaxDynamicSharedMemorySize,
                         FA_SMEM);

    /* projections: Q, K, V all write bf16 hi/lo split directly */
    split_kernel<<<M_TOT * D / 1024, 256>>>(query, ahi, alo);
    wsplitT_kernel<<<gw, bw>>>(Wq, whi, wlo);
    gemm_mma<<<gg, 256>>>(ahi, alo, whi, wlo, bq, nullptr, qhi, qlo);

    split_kernel<<<M_TOT * D / 1024, 256>>>(key, ahi, alo);
    wsplitT_kernel<<<gw, bw>>>(Wk, whi, wlo);
    gemm_mma<<<gg, 256>>>(ahi, alo, whi, wlo, bk, nullptr, khi, klo);

    split_kernel<<<M_TOT * D / 1024, 256>>>(value, ahi, alo);
    wsplitT_kernel<<<gw, bw>>>(Wv, whi, wlo);
    gemm_mma<<<gg, 256>>>(ahi, alo, whi, wlo, bv, nullptr, vhi, vlo);

    /* attention: P precompute, then fused flash kernel -> O split in ahi/alo */
    split_kernel<<<D * D / 1024, 256>>>(rel, rhi, rlo);
    pqr_kernel<<<dim3(S / 128, BB * H), 256, PQR_SMEM>>>(qhi, qlo, rhi, rlo);
    fused_attn<<<dim3(S / 128, BB * H), 256, FA_SMEM>>>(qhi, qlo, khi, klo,
                                                        vhi, vlo, ahi, alo);

    /* output projection */
    wsplitT_kernel<<<gw, bw>>>(Wo, whi, wlo);
    gemm_mma<<<gg, 256>>>(ahi, alo, whi, wlo, bo, (float*)d_out,
                          nullptr, nullptr);
}